// round 14
// baseline (speedup 1.0000x reference)
#include <cuda_runtime.h>
#include <cuda_bf16.h>
#include <cuda_fp16.h>

#define CC 512
#define NP 4096
#define KK 64
#define BB 16
#define NSPLIT 4
#define EPSF 1e-6f

typedef unsigned long long u64;
typedef unsigned int u32;
typedef unsigned short u16;

// ---------------- scratch (static device globals) ---------------------------
__device__ u16 g_xh[(size_t)BB * CC * NP];   // x hi fp16 (b,c,p)
__device__ u16 g_xl[(size_t)BB * CC * NP];   // x lo fp16
__device__ u16 g_wf1[(size_t)CC * CC];       // w1 fp16 single
__device__ u16 g_wf2[(size_t)CC * CC];       // w2 fp16 single
__device__ u16 g_muh[(size_t)CC * KK], g_mul[(size_t)CC * KK];   // fp16 hi/lo
__device__ u16 g_xfh[(size_t)BB * CC * NP];  // conv1 out hi fp16 (b,c,p)
__device__ u16 g_xfl[(size_t)BB * CC * NP];
__device__ u16 g_zh[(size_t)BB * NP * KK];   // z hi fp16 (b,p,k)
__device__ u16 g_zl[(size_t)BB * NP * KK];
__device__ u16 g_mh[(size_t)BB * CC * KK];   // m hi fp16 (b,c,k)
__device__ u16 g_ml[(size_t)BB * CC * KK];
__device__ u16 g_rech[(size_t)BB * CC * NP]; // relu(rec) fp16 single (b,c,p)
__device__ float g_mpart[(size_t)NSPLIT * BB * CC * KK];

// ---------------- helpers ----------------------------------------------------
__device__ __forceinline__ u32 smem_u32(const void* p) {
    u32 a;
    asm("{ .reg .u64 t; cvta.to.shared.u64 t, %1; cvt.u32.u64 %0, t; }"
        : "=r"(a) : "l"(p));
    return a;
}
__device__ __forceinline__ void ldsm4(u32* r, u32 addr) {
    asm volatile("ldmatrix.sync.aligned.m8n8.x4.shared.b16 {%0,%1,%2,%3}, [%4];"
                 : "=r"(r[0]), "=r"(r[1]), "=r"(r[2]), "=r"(r[3]) : "r"(addr));
}
__device__ __forceinline__ void ldsm4t(u32* r, u32 addr) {
    asm volatile("ldmatrix.sync.aligned.m8n8.x4.trans.shared.b16 {%0,%1,%2,%3}, [%4];"
                 : "=r"(r[0]), "=r"(r[1]), "=r"(r[2]), "=r"(r[3]) : "r"(addr));
}
__device__ __forceinline__ void mma_fp16(float* d, const u32* a, const u32* b) {
    asm volatile(
        "mma.sync.aligned.m16n8k16.row.col.f32.f16.f16.f32 "
        "{%0,%1,%2,%3}, {%4,%5,%6,%7}, {%8,%9}, {%0,%1,%2,%3};"
        : "+f"(d[0]), "+f"(d[1]), "+f"(d[2]), "+f"(d[3])
        : "r"(a[0]), "r"(a[1]), "r"(a[2]), "r"(a[3]), "r"(b[0]), "r"(b[1]));
}
__device__ __forceinline__ void split2h(float v0, float v1, u32& hi, u32& lo) {
    __half h0 = __float2half_rn(v0);
    __half h1 = __float2half_rn(v1);
    __half l0 = __float2half_rn(v0 - __half2float(h0));
    __half l1 = __float2half_rn(v1 - __half2float(h1));
    hi = (u32)__half_as_ushort(h0) | ((u32)__half_as_ushort(h1) << 16);
    lo = (u32)__half_as_ushort(l0) | ((u32)__half_as_ushort(l1) << 16);
}
__device__ __forceinline__ u32 pack2h(float v0, float v1) {
    __half h0 = __float2half_rn(v0);
    __half h1 = __float2half_rn(v1);
    return (u32)__half_as_ushort(h0) | ((u32)__half_as_ushort(h1) << 16);
}
__device__ __forceinline__ void cpa16(u32 dst, const void* src) {
    asm volatile("cp.async.cg.shared.global [%0], [%1], 16;"
                 :: "r"(dst), "l"(src));
}
#define CPA_COMMIT() asm volatile("cp.async.commit_group;")
#define CPA_WAIT(n)  asm volatile("cp.async.wait_group %0;" :: "n"(n))

// ---------------- fused convert kernel (x + w1/w2 + mu in one launch) -------
#define XBLOCKS 32768          // BB*CC*NP / 1024
#define WBLOCKS 512            // CC*CC / 512
#define MUBLOCKS 64            // CC*KK / 512
__global__ void kcvt_all(const float* __restrict__ x,
                         const float* __restrict__ w1,
                         const float* __restrict__ w2,
                         const float* __restrict__ mu)
{
    int bx = blockIdx.x;
    if (bx < XBLOCKS) {
        size_t i4 = ((size_t)bx * 256 + threadIdx.x) * 4;
        float4 v = *(const float4*)&x[i4];
        u32 h0, l0, h1, l1;
        split2h(v.x, v.y, h0, l0);
        split2h(v.z, v.w, h1, l1);
        *(uint2*)&g_xh[i4] = make_uint2(h0, h1);
        *(uint2*)&g_xl[i4] = make_uint2(l0, l1);
    } else if (bx < XBLOCKS + WBLOCKS) {
        size_t i2 = ((size_t)(bx - XBLOCKS) * 256 + threadIdx.x) * 2;
        *(u32*)&g_wf1[i2] = pack2h(w1[i2], w1[i2 + 1]);
        *(u32*)&g_wf2[i2] = pack2h(w2[i2], w2[i2 + 1]);
    } else {
        size_t i2 = ((size_t)(bx - XBLOCKS - WBLOCKS) * 256 + threadIdx.x) * 2;
        u32 h, l;
        split2h(mu[i2], mu[i2 + 1], h, l);
        *(u32*)&g_muh[i2] = h; *(u32*)&g_mul[i2] = l;
    }
}

// ---------------- conv GEMM v7: 256 thr, 8 warps (2o x 4p), 4-stage ---------
// EPI=0: B = x hi/lo (2-term), bias -> g_xfh/g_xfl fp16 split
// EPI=1: B = rec single fp16 (1-term), BN -> OUT fp32
#define APITCH 40
#define BPITCH 136
#define AH_OFF 0
#define BH_OFF 10240
#define BL_OFF 18944
#define STAGE_B 27648
#define NSTAGE 4
#define NCH 16
#define HCONV_SMEM (STAGE_B * NSTAGE)

template <int EPI>
__global__ __launch_bounds__(256, 2)
void hconv(float* __restrict__ OUT,
           const float* __restrict__ e0, const float* __restrict__ e1,
           const float* __restrict__ e2, const float* __restrict__ e3)
{
    extern __shared__ __align__(16) char dsm[];
    const u32 sb = smem_u32(dsm);

    const int p0 = blockIdx.x * 128;
    const int o0 = blockIdx.y * 128;
    const int b  = blockIdx.z;
    const int tid = threadIdx.x;
    const int lane = tid & 31, wid = tid >> 5;
    const int ob = (wid & 1) * 64, pb = (wid >> 1) * 32;

    const u16* WH = (EPI == 0) ? g_wf1 : g_wf2;
    const u16* IH = ((EPI == 0) ? g_xh : g_rech) + (size_t)b * CC * NP;
    const u16* IL = g_xl + (size_t)b * CC * NP;   // only used when EPI == 0

    float acc[4][4][4];
#pragma unroll
    for (int mf = 0; mf < 4; mf++)
#pragma unroll
        for (int nf = 0; nf < 4; nf++)
#pragma unroll
            for (int q = 0; q < 4; q++) acc[mf][nf][q] = 0.f;

    const int arow = tid >> 1, ag = (tid & 1) * 16;
    const int brow = tid >> 4, bu = (tid & 15) * 8;

#define LOAD_CHUNK(st, c0)                                                      \
    do {                                                                        \
        u32 base = sb + (st) * STAGE_B;                                         \
        cpa16(base + AH_OFF + (arow * APITCH + ag) * 2,                         \
              WH + (size_t)(o0 + arow) * CC + (c0) + ag);                       \
        cpa16(base + AH_OFF + (arow * APITCH + ag + 8) * 2,                     \
              WH + (size_t)(o0 + arow) * CC + (c0) + ag + 8);                   \
        _Pragma("unroll")                                                       \
        for (int i = 0; i < 2; i++) {                                           \
            int r = brow + i * 16;                                              \
            cpa16(base + BH_OFF + (r * BPITCH + bu) * 2,                        \
                  IH + (size_t)((c0) + r) * NP + p0 + bu);                      \
            if (EPI == 0)                                                       \
                cpa16(base + BL_OFF + (r * BPITCH + bu) * 2,                    \
                      IL + (size_t)((c0) + r) * NP + p0 + bu);                  \
        }                                                                       \
        CPA_COMMIT();                                                           \
    } while (0)

    LOAD_CHUNK(0, 0);
    LOAD_CHUNK(1, 32);
    LOAD_CHUNK(2, 64);

    const u32 a_lane = ((ob + (lane & 15)) * APITCH + (lane >> 4) * 8) * 2;
    const u32 b_rbase = (lane & 7) + ((lane >> 3) & 1) * 8;
    const u32 b_col   = pb + ((lane >> 4) & 1) * 8;

    for (int ch = 0; ch < NCH; ch++) {
        if (ch < NCH - 2)      { CPA_WAIT(2); }
        else if (ch == NCH - 2){ CPA_WAIT(1); }
        else                   { CPA_WAIT(0); }
        __syncthreads();
        if (ch < NCH - 3) LOAD_CHUNK((ch + 3) % NSTAGE, (ch + 3) * 32);

        const u32 stb = sb + (ch % NSTAGE) * STAGE_B;
#pragma unroll
        for (int ks = 0; ks < 2; ks++) {
            u32 ah[4][4];
            const u32 abase = stb + a_lane + ks * 32;
#pragma unroll
            for (int mf = 0; mf < 4; mf++)
                ldsm4(ah[mf], abase + AH_OFF + mf * (16 * APITCH * 2));
            const u32 brw = ks * 16 + b_rbase;
            const u32 bbase = stb + (brw * BPITCH + b_col) * 2;
#pragma unroll
            for (int pr = 0; pr < 2; pr++) {
                u32 bh[4], bl[4];
                ldsm4t(bh, bbase + BH_OFF + pr * 32);
                if (EPI == 0) ldsm4t(bl, bbase + BL_OFF + pr * 32);
#pragma unroll
                for (int mf = 0; mf < 4; mf++) {
#pragma unroll
                    for (int hn = 0; hn < 2; hn++) {
                        float* a = acc[mf][pr * 2 + hn];
                        mma_fp16(a, ah[mf], &bh[hn * 2]);
                        if (EPI == 0) mma_fp16(a, ah[mf], &bl[hn * 2]);
                    }
                }
            }
        }
    }

    const int g = lane >> 2, tg = lane & 3;
#pragma unroll
    for (int mf = 0; mf < 4; mf++) {
        int o_lo = o0 + ob + mf * 16 + g;
        int o_hi = o_lo + 8;
        if (EPI == 0) {
            float add_lo = e0[o_lo], add_hi = e0[o_hi];
            u16* xfh = g_xfh + (size_t)b * CC * NP;
            u16* xfl = g_xfl + (size_t)b * CC * NP;
#pragma unroll
            for (int nf = 0; nf < 4; nf++) {
                int pc = p0 + pb + nf * 8 + tg * 2;
                u32 h, l;
                split2h(acc[mf][nf][0] + add_lo, acc[mf][nf][1] + add_lo, h, l);
                *(u32*)&xfh[(size_t)o_lo * NP + pc] = h;
                *(u32*)&xfl[(size_t)o_lo * NP + pc] = l;
                split2h(acc[mf][nf][2] + add_hi, acc[mf][nf][3] + add_hi, h, l);
                *(u32*)&xfh[(size_t)o_hi * NP + pc] = h;
                *(u32*)&xfl[(size_t)o_hi * NP + pc] = l;
            }
        } else {
            float mul_lo = e0[o_lo] * rsqrtf(e3[o_lo] + 1e-5f);
            float add_lo = e1[o_lo] - e2[o_lo] * mul_lo;
            float mul_hi = e0[o_hi] * rsqrtf(e3[o_hi] + 1e-5f);
            float add_hi = e1[o_hi] - e2[o_hi] * mul_hi;
            float* outb = OUT + (size_t)b * CC * NP;
#pragma unroll
            for (int nf = 0; nf < 4; nf++) {
                int pc = p0 + pb + nf * 8 + tg * 2;
                float2 v0, v1;
                v0.x = acc[mf][nf][0] * mul_lo + add_lo;
                v0.y = acc[mf][nf][1] * mul_lo + add_lo;
                v1.x = acc[mf][nf][2] * mul_hi + add_hi;
                v1.y = acc[mf][nf][3] * mul_hi + add_hi;
                *(float2*)&outb[(size_t)o_lo * NP + pc] = v0;
                *(float2*)&outb[(size_t)o_hi * NP + pc] = v1;
            }
        }
    }
#undef LOAD_CHUNK
}

// ---------------- kz v4: 4 p-warps x 2 k-warps, fp16 3-term -----------------
__global__ __launch_bounds__(256, 2)
void kz_kernel(int use_gm)
{
    __shared__ __align__(16) u16 Xh[32 * 136], Xl[32 * 136]; // (c32, p128)
    __shared__ __align__(16) u16 Mh[32 * 72],  Ml[32 * 72];  // (c32, k64)
    __shared__ float sred[2][128];

    const int p0 = blockIdx.x * 128;
    const int b  = blockIdx.y;
    const int tid = threadIdx.x;
    const int lane = tid & 31, wid = tid >> 5;
    const int pg = wid & 3, kw = wid >> 2;
    const int pwb = pg * 32;

    const u16* XH = g_xfh + (size_t)b * CC * NP;
    const u16* XL = g_xfl + (size_t)b * CC * NP;
    const u16* MH = use_gm ? (g_mh + (size_t)b * CC * KK) : g_muh;
    const u16* ML = use_gm ? (g_ml + (size_t)b * CC * KK) : g_mul;

    float acc[2][4][4];
#pragma unroll
    for (int mf = 0; mf < 2; mf++)
#pragma unroll
        for (int nf = 0; nf < 4; nf++)
#pragma unroll
            for (int q = 0; q < 4; q++) acc[mf][nf][q] = 0.f;

    const u32 sxh = smem_u32(Xh), sxl = smem_u32(Xl);
    const u32 smh = smem_u32(Mh), sml = smem_u32(Ml);

    const int xr0 = tid >> 4,           xg0 = (tid & 15) * 8;
    const int xr1 = (tid + 256) >> 4,   xg1 = (tid & 15) * 8;
    const int mr  = tid >> 3,           mg  = (tid & 7) * 8;

    uint4 pxh[2], pxl[2], pmh, pml;
#define KZ_PREFETCH(c0)                                                        \
    do {                                                                       \
        pxh[0] = *(const uint4*)(XH + (size_t)((c0) + xr0) * NP + p0 + xg0);   \
        pxh[1] = *(const uint4*)(XH + (size_t)((c0) + xr1) * NP + p0 + xg1);   \
        pxl[0] = *(const uint4*)(XL + (size_t)((c0) + xr0) * NP + p0 + xg0);   \
        pxl[1] = *(const uint4*)(XL + (size_t)((c0) + xr1) * NP + p0 + xg1);   \
        pmh    = *(const uint4*)(MH + (size_t)((c0) + mr) * KK + mg);          \
        pml    = *(const uint4*)(ML + (size_t)((c0) + mr) * KK + mg);          \
    } while (0)

    KZ_PREFETCH(0);

    for (int c0 = 0; c0 < CC; c0 += 32) {
        __syncthreads();
        *(uint4*)&Xh[xr0 * 136 + xg0] = pxh[0];
        *(uint4*)&Xh[xr1 * 136 + xg1] = pxh[1];
        *(uint4*)&Xl[xr0 * 136 + xg0] = pxl[0];
        *(uint4*)&Xl[xr1 * 136 + xg1] = pxl[1];
        *(uint4*)&Mh[mr * 72 + mg] = pmh;
        *(uint4*)&Ml[mr * 72 + mg] = pml;
        __syncthreads();
        if (c0 + 32 < CC) KZ_PREFETCH(c0 + 32);

#pragma unroll
        for (int ks = 0; ks < 2; ks++) {
            u32 ah[2][4], al[2][4];
#pragma unroll
            for (int mf = 0; mf < 2; mf++) {
                u32 row = ks * 16 + (lane & 7) + ((lane >> 4) & 1) * 8;
                u32 col = pwb + mf * 16 + ((lane >> 3) & 1) * 8;
                u32 off = (row * 136 + col) << 1;
                ldsm4t(ah[mf], sxh + off);
                ldsm4t(al[mf], sxl + off);
            }
            u32 bh[2][4], bl[2][4];
            {
                u32 row = ks * 16 + (lane & 7) + ((lane >> 3) & 1) * 8;
                u32 col = kw * 32 + ((lane >> 4) & 1) * 8;
#pragma unroll
                for (int pr = 0; pr < 2; pr++) {
                    u32 off = (row * 72 + col + pr * 16) << 1;
                    ldsm4t(bh[pr], smh + off);
                    ldsm4t(bl[pr], sml + off);
                }
            }
#pragma unroll
            for (int mf = 0; mf < 2; mf++)
#pragma unroll
                for (int nf = 0; nf < 4; nf++) {
                    const u32* bhp = &bh[nf >> 1][(nf & 1) * 2];
                    const u32* blp = &bl[nf >> 1][(nf & 1) * 2];
                    mma_fp16(acc[mf][nf], ah[mf], bhp);
                    mma_fp16(acc[mf][nf], ah[mf], blp);
                    mma_fp16(acc[mf][nf], al[mf], bhp);
                }
        }
    }
#undef KZ_PREFETCH

    // ---- softmax over k=64 split across 2 k-warps ----
    const int gr = lane >> 2, tg = lane & 3;
    float pm[2][2];
#pragma unroll
    for (int mf = 0; mf < 2; mf++) {
        float m0 = -1e30f, m1 = -1e30f;
#pragma unroll
        for (int nf = 0; nf < 4; nf++) {
            m0 = fmaxf(m0, fmaxf(acc[mf][nf][0], acc[mf][nf][1]));
            m1 = fmaxf(m1, fmaxf(acc[mf][nf][2], acc[mf][nf][3]));
        }
#pragma unroll
        for (int s = 1; s < 4; s <<= 1) {
            m0 = fmaxf(m0, __shfl_xor_sync(0xffffffffu, m0, s));
            m1 = fmaxf(m1, __shfl_xor_sync(0xffffffffu, m1, s));
        }
        pm[mf][0] = m0; pm[mf][1] = m1;
    }
    if (tg == 0) {
#pragma unroll
        for (int mf = 0; mf < 2; mf++) {
            sred[kw][pwb + mf * 16 + gr]     = pm[mf][0];
            sred[kw][pwb + mf * 16 + gr + 8] = pm[mf][1];
        }
    }
    __syncthreads();
    float fm[2][2];
#pragma unroll
    for (int mf = 0; mf < 2; mf++) {
        fm[mf][0] = fmaxf(pm[mf][0], sred[kw ^ 1][pwb + mf * 16 + gr]);
        fm[mf][1] = fmaxf(pm[mf][1], sred[kw ^ 1][pwb + mf * 16 + gr + 8]);
    }
    __syncthreads();
    float ps[2][2];
#pragma unroll
    for (int mf = 0; mf < 2; mf++) {
        float s0 = 0.f, s1 = 0.f;
#pragma unroll
        for (int nf = 0; nf < 4; nf++) {
            acc[mf][nf][0] = expf(acc[mf][nf][0] - fm[mf][0]); s0 += acc[mf][nf][0];
            acc[mf][nf][1] = expf(acc[mf][nf][1] - fm[mf][0]); s0 += acc[mf][nf][1];
            acc[mf][nf][2] = expf(acc[mf][nf][2] - fm[mf][1]); s1 += acc[mf][nf][2];
            acc[mf][nf][3] = expf(acc[mf][nf][3] - fm[mf][1]); s1 += acc[mf][nf][3];
        }
#pragma unroll
        for (int s = 1; s < 4; s <<= 1) {
            s0 += __shfl_xor_sync(0xffffffffu, s0, s);
            s1 += __shfl_xor_sync(0xffffffffu, s1, s);
        }
        ps[mf][0] = s0; ps[mf][1] = s1;
    }
    if (tg == 0) {
#pragma unroll
        for (int mf = 0; mf < 2; mf++) {
            sred[kw][pwb + mf * 16 + gr]     = ps[mf][0];
            sred[kw][pwb + mf * 16 + gr + 8] = ps[mf][1];
        }
    }
    __syncthreads();
#pragma unroll
    for (int mf = 0; mf < 2; mf++) {
        float inv0 = 1.f / (ps[mf][0] + sred[kw ^ 1][pwb + mf * 16 + gr]);
        float inv1 = 1.f / (ps[mf][1] + sred[kw ^ 1][pwb + mf * 16 + gr + 8]);
        size_t prow_lo = (size_t)(b * NP + p0 + pwb + mf * 16 + gr) * KK;
        size_t prow_hi = prow_lo + (size_t)8 * KK;
#pragma unroll
        for (int nf = 0; nf < 4; nf++) {
            int kc = kw * 32 + nf * 8 + tg * 2;
            u32 h, l;
            split2h(acc[mf][nf][0] * inv0, acc[mf][nf][1] * inv0, h, l);
            *(u32*)&g_zh[prow_lo + kc] = h;
            *(u32*)&g_zl[prow_lo + kc] = l;
            split2h(acc[mf][nf][2] * inv1, acc[mf][nf][3] * inv1, h, l);
            *(u32*)&g_zh[prow_hi + kc] = h;
            *(u32*)&g_zl[prow_hi + kc] = l;
        }
    }
}

// ---------------- km v4: 4 c-warps x 2 k-warps, fp16 3-term -----------------
__global__ __launch_bounds__(256, 2)
void km_kernel()
{
    __shared__ __align__(16) u16 Ah[128 * 40], Al[128 * 40]; // (c128, p32)
    __shared__ __align__(16) u16 Zh[32 * 72],  Zl[32 * 72];  // (p32, k64)

    const int ct0 = blockIdx.x * 128;
    const int b   = blockIdx.y;
    const int s   = blockIdx.z;
    const int ps0 = s * (NP / NSPLIT);
    const int tid = threadIdx.x;
    const int lane = tid & 31, wid = tid >> 5;
    const int cw = wid & 3, kw = wid >> 2;

    const u16* XH = g_xfh + (size_t)b * CC * NP;
    const u16* XL = g_xfl + (size_t)b * CC * NP;
    const u16* ZH = g_zh + (size_t)b * NP * KK;
    const u16* ZL = g_zl + (size_t)b * NP * KK;

    float acc[2][4][4];
#pragma unroll
    for (int mf = 0; mf < 2; mf++)
#pragma unroll
        for (int nf = 0; nf < 4; nf++)
#pragma unroll
            for (int q = 0; q < 4; q++) acc[mf][nf][q] = 0.f;

    const u32 sah = smem_u32(Ah), sal = smem_u32(Al);
    const u32 szh = smem_u32(Zh), szl = smem_u32(Zl);

    const int ar0 = tid >> 2,         ag0 = (tid & 3) * 8;
    const int ar1 = (tid + 256) >> 2, ag1 = (tid & 3) * 8;
    const int zr  = tid >> 3,         zg  = (tid & 7) * 8;

    uint4 pah[2], pal[2], pzh, pzl;
#define KM_PREFETCH(pc0)                                                       \
    do {                                                                       \
        pah[0] = *(const uint4*)(XH + (size_t)(ct0 + ar0) * NP + (pc0) + ag0); \
        pah[1] = *(const uint4*)(XH + (size_t)(ct0 + ar1) * NP + (pc0) + ag1); \
        pal[0] = *(const uint4*)(XL + (size_t)(ct0 + ar0) * NP + (pc0) + ag0); \
        pal[1] = *(const uint4*)(XL + (size_t)(ct0 + ar1) * NP + (pc0) + ag1); \
        pzh    = *(const uint4*)(ZH + (size_t)((pc0) + zr) * KK + zg);         \
        pzl    = *(const uint4*)(ZL + (size_t)((pc0) + zr) * KK + zg);         \
    } while (0)

    KM_PREFETCH(ps0);

    for (int pc0 = ps0; pc0 < ps0 + NP / NSPLIT; pc0 += 32) {
        __syncthreads();
        *(uint4*)&Ah[ar0 * 40 + ag0] = pah[0];
        *(uint4*)&Ah[ar1 * 40 + ag1] = pah[1];
        *(uint4*)&Al[ar0 * 40 + ag0] = pal[0];
        *(uint4*)&Al[ar1 * 40 + ag1] = pal[1];
        *(uint4*)&Zh[zr * 72 + zg] = pzh;
        *(uint4*)&Zl[zr * 72 + zg] = pzl;
        __syncthreads();
        if (pc0 + 32 < ps0 + NP / NSPLIT) KM_PREFETCH(pc0 + 32);

#pragma unroll
        for (int ks = 0; ks < 2; ks++) {
            u32 ah[2][4], al[2][4];
#pragma unroll
            for (int mf = 0; mf < 2; mf++) {
                u32 off = (((cw * 32 + mf * 16 + (lane & 15)) * 40 +
                            ks * 16 + (lane >> 4) * 8)) << 1;
                ldsm4(ah[mf], sah + off);
                ldsm4(al[mf], sal + off);
            }
            u32 bh[2][4], bl[2][4];
            {
                u32 row = ks * 16 + (lane & 7) + ((lane >> 3) & 1) * 8;
                u32 col = kw * 32 + ((lane >> 4) & 1) * 8;
#pragma unroll
                for (int pr = 0; pr < 2; pr++) {
                    u32 off = (row * 72 + col + pr * 16) << 1;
                    ldsm4t(bh[pr], szh + off);
                    ldsm4t(bl[pr], szl + off);
                }
            }
#pragma unroll
            for (int mf = 0; mf < 2; mf++)
#pragma unroll
                for (int nf = 0; nf < 4; nf++) {
                    const u32* bhp = &bh[nf >> 1][(nf & 1) * 2];
                    const u32* blp = &bl[nf >> 1][(nf & 1) * 2];
                    mma_fp16(acc[mf][nf], ah[mf], bhp);
                    mma_fp16(acc[mf][nf], ah[mf], blp);
                    mma_fp16(acc[mf][nf], al[mf], bhp);
                }
        }
    }
#undef KM_PREFETCH

    const int gr = lane >> 2, tg = lane & 3;
    float* out = g_mpart + ((size_t)(s * BB + b) * CC + ct0 + cw * 32) * KK;
#pragma unroll
    for (int mf = 0; mf < 2; mf++)
#pragma unroll
        for (int nf = 0; nf < 4; nf++) {
            int kc = kw * 32 + nf * 8 + tg * 2;
            int r0 = mf * 16 + gr;
            *(float2*)&out[(size_t)r0 * KK + kc] =
                make_float2(acc[mf][nf][0], acc[mf][nf][1]);
            *(float2*)&out[(size_t)(r0 + 8) * KK + kc] =
                make_float2(acc[mf][nf][2], acc[mf][nf][3]);
        }
}

// ---------------- fused norm: grid (4, BB), emits fp16 hi/lo ----------------
__global__ __launch_bounds__(1024)
void knorm_fused()
{
    const int b  = blockIdx.y;
    const int k0 = blockIdx.x * 16;
    const int tid = threadIdx.x;
    const int kl = tid & 15;
    const int cg = tid >> 4;            // 0..63, each owns 8 c-rows

    __shared__ float red[64][17];

    const size_t base = (size_t)b * CC * KK;
    const int k = k0 + kl;
    float v[8];
    float ss = 0.f;
#pragma unroll
    for (int i = 0; i < 8; i++) {
        size_t off = base + (size_t)(cg * 8 + i) * KK + k;
        float t = 0.f;
#pragma unroll
        for (int s = 0; s < NSPLIT; s++)
            t += g_mpart[(size_t)s * (BB * CC * KK) + off];
        v[i] = t;
        ss += t * t;
    }
    red[cg][kl] = ss;
    __syncthreads();
#pragma unroll
    for (int s = 32; s > 0; s >>= 1) {
        if (cg < s) red[cg][kl] += red[cg + s][kl];
        __syncthreads();
    }
    const float inv = 1.f / (EPSF + sqrtf(red[0][kl]));
    u16* mh = g_mh + base;
    u16* ml = g_ml + base;
#pragma unroll
    for (int i = 0; i < 8; i++) {
        float sv = v[i] * inv;
        __half h = __float2half_rn(sv);
        __half l = __float2half_rn(sv - __half2float(h));
        size_t off = (size_t)(cg * 8 + i) * KK + k;
        mh[off] = __half_as_ushort(h);
        ml[off] = __half_as_ushort(l);
    }
}

// ---------------- krec: rec = relu(m @ z^T), m single fp16, 2-term ----------
__global__ __launch_bounds__(256, 2)
void krec_kernel()
{
    __shared__ __align__(16) u16 Ah[128 * 40];               // (c128, k32) m hi
    __shared__ __align__(16) u16 Bh[128 * 40], Bl[128 * 40]; // (p128, k32)

    const int p0  = blockIdx.x * 128;
    const int ct0 = blockIdx.y * 128;
    const int b   = blockIdx.z;
    const int tid = threadIdx.x;
    const int lane = tid & 31, wid = tid >> 5;
    const int wm = wid & 1, wn = wid >> 1;
    const int cb = wm * 64, pb = wn * 32;

    const u16* MH = g_mh + (size_t)b * CC * KK;
    const u16* ZH = g_zh + (size_t)b * NP * KK;
    const u16* ZL = g_zl + (size_t)b * NP * KK;

    float acc[4][4][4];
#pragma unroll
    for (int mf = 0; mf < 4; mf++)
#pragma unroll
        for (int nf = 0; nf < 4; nf++)
#pragma unroll
            for (int q = 0; q < 4; q++) acc[mf][nf][q] = 0.f;

    const u32 sah = smem_u32(Ah);
    const u32 sbh = smem_u32(Bh), sbl = smem_u32(Bl);

    for (int kc0 = 0; kc0 < KK; kc0 += 32) {
#pragma unroll
        for (int it = 0; it < 2; it++) {
            int lin = tid + it * 256;
            int r = lin >> 2, g = lin & 3;
            *(uint4*)&Ah[r * 40 + g * 8] =
                *(const uint4*)(MH + (size_t)(ct0 + r) * KK + kc0 + g * 8);
        }
#pragma unroll
        for (int it = 0; it < 2; it++) {
            int lin = tid + it * 256;
            int r = lin >> 2, g = lin & 3;
            *(uint4*)&Bh[r * 40 + g * 8] =
                *(const uint4*)(ZH + (size_t)(p0 + r) * KK + kc0 + g * 8);
            *(uint4*)&Bl[r * 40 + g * 8] =
                *(const uint4*)(ZL + (size_t)(p0 + r) * KK + kc0 + g * 8);
        }
        __syncthreads();
#pragma unroll
        for (int ks = 0; ks < 2; ks++) {
            u32 ah[4][4];
            u32 a_off = (((cb + (lane & 15)) * 40 + ks * 16 + (lane >> 4) * 8)) << 1;
#pragma unroll
            for (int mf = 0; mf < 4; mf++)
                ldsm4(ah[mf], sah + a_off + mf * (16 * 40 * 2));
            u32 bh[2][4], bl[2][4];
            u32 brow = pb + ((lane >> 4) & 1) * 8 + (lane & 7);
            u32 bcol = ks * 16 + ((lane >> 3) & 1) * 8;
#pragma unroll
            for (int pr = 0; pr < 2; pr++) {
                u32 boff = ((brow + pr * 16) * 40 + bcol) << 1;
                ldsm4(bh[pr], sbh + boff);
                ldsm4(bl[pr], sbl + boff);
            }
#pragma unroll
            for (int mf = 0; mf < 4; mf++)
#pragma unroll
                for (int nf = 0; nf < 4; nf++) {
                    const u32* bhp = &bh[nf >> 1][(nf & 1) * 2];
                    const u32* blp = &bl[nf >> 1][(nf & 1) * 2];
                    mma_fp16(acc[mf][nf], ah[mf], bhp);
                    mma_fp16(acc[mf][nf], ah[mf], blp);
                }
        }
        __syncthreads();
    }

    const int g = lane >> 2, tg = lane & 3;
    u16* rh = g_rech + (size_t)b * CC * NP;
#pragma unroll
    for (int mf = 0; mf < 4; mf++) {
        int c_lo = ct0 + cb + mf * 16 + g;
        int c_hi = c_lo + 8;
#pragma unroll
        for (int nf = 0; nf < 4; nf++) {
            int pc = p0 + pb + nf * 8 + tg * 2;
            *(u32*)&rh[(size_t)c_lo * NP + pc] =
                pack2h(fmaxf(acc[mf][nf][0], 0.f), fmaxf(acc[mf][nf][1], 0.f));
            *(u32*)&rh[(size_t)c_hi * NP + pc] =
                pack2h(fmaxf(acc[mf][nf][2], 0.f), fmaxf(acc[mf][nf][3], 0.f));
        }
    }
}

// ---------------- launch ----------------------------------------------------
extern "C" void kernel_launch(void* const* d_in, const int* in_sizes, int n_in,
                              void* d_out, int out_size)
{
    (void)in_sizes; (void)n_in; (void)out_size;
    const float* x     = (const float*)d_in[0];
    const float* w1    = (const float*)d_in[1];
    const float* b1    = (const float*)d_in[2];
    const float* mu    = (const float*)d_in[3];
    const float* w2    = (const float*)d_in[4];
    const float* gamma = (const float*)d_in[5];
    const float* beta  = (const float*)d_in[6];
    const float* mean  = (const float*)d_in[7];
    const float* var   = (const float*)d_in[8];
    float* out = (float*)d_out;

    cudaFuncSetAttribute(hconv<0>, cudaFuncAttributeMaxDynamicSharedMemorySize,
                         HCONV_SMEM);
    cudaFuncSetAttribute(hconv<1>, cudaFuncAttributeMaxDynamicSharedMemorySize,
                         HCONV_SMEM);

    kcvt_all<<<XBLOCKS + WBLOCKS + MUBLOCKS, 256>>>(x, w1, w2, mu);

    hconv<0><<<dim3(NP / 128, CC / 128, BB), 256, HCONV_SMEM>>>(
        nullptr, b1, nullptr, nullptr, nullptr);

    for (int st = 0; st < 3; st++) {
        kz_kernel<<<dim3(NP / 128, BB), 256>>>(st > 0 ? 1 : 0);
        km_kernel<<<dim3(CC / 128, BB, NSPLIT), 256>>>();
        knorm_fused<<<dim3(4, BB), 1024>>>();
    }

    krec_kernel<<<dim3(NP / 128, CC / 128, BB), 256>>>();

    hconv<1><<<dim3(NP / 128, CC / 128, BB), 256, HCONV_SMEM>>>(
        out, gamma, beta, mean, var);
}

// round 15
// speedup vs baseline: 1.0369x; 1.0369x over previous
#include <cuda_runtime.h>
#include <cuda_bf16.h>
#include <cuda_fp16.h>

#define CC 512
#define NP 4096
#define KK 64
#define BB 16
#define NSPLIT 4
#define EPSF 1e-6f

typedef unsigned long long u64;
typedef unsigned int u32;
typedef unsigned short u16;

// ---------------- scratch (static device globals) ---------------------------
__device__ u16 g_xh[(size_t)BB * CC * NP];   // x hi fp16 (b,c,p)
__device__ u16 g_xl[(size_t)BB * CC * NP];   // x lo fp16
__device__ u16 g_wf1[(size_t)CC * CC];       // w1 fp16 single
__device__ u16 g_wf2[(size_t)CC * CC];       // w2 fp16 single
__device__ u16 g_muh[(size_t)CC * KK], g_mul[(size_t)CC * KK];   // fp16 hi/lo
__device__ u16 g_xfh[(size_t)BB * CC * NP];  // conv1 out hi fp16 (b,c,p)
__device__ u16 g_xfl[(size_t)BB * CC * NP];
__device__ u16 g_zh[(size_t)BB * NP * KK];   // z hi fp16 (b,p,k)
__device__ u16 g_zl[(size_t)BB * NP * KK];
__device__ u16 g_mh[(size_t)BB * CC * KK];   // m hi fp16 (b,c,k)
__device__ u16 g_ml[(size_t)BB * CC * KK];
__device__ u16 g_rech[(size_t)BB * CC * NP]; // relu(rec) fp16 single (b,c,p)
__device__ float g_mpart[(size_t)NSPLIT * BB * CC * KK];

// ---------------- helpers ----------------------------------------------------
__device__ __forceinline__ u32 smem_u32(const void* p) {
    u32 a;
    asm("{ .reg .u64 t; cvta.to.shared.u64 t, %1; cvt.u32.u64 %0, t; }"
        : "=r"(a) : "l"(p));
    return a;
}
__device__ __forceinline__ void ldsm4(u32* r, u32 addr) {
    asm volatile("ldmatrix.sync.aligned.m8n8.x4.shared.b16 {%0,%1,%2,%3}, [%4];"
                 : "=r"(r[0]), "=r"(r[1]), "=r"(r[2]), "=r"(r[3]) : "r"(addr));
}
__device__ __forceinline__ void ldsm4t(u32* r, u32 addr) {
    asm volatile("ldmatrix.sync.aligned.m8n8.x4.trans.shared.b16 {%0,%1,%2,%3}, [%4];"
                 : "=r"(r[0]), "=r"(r[1]), "=r"(r[2]), "=r"(r[3]) : "r"(addr));
}
__device__ __forceinline__ void mma_fp16(float* d, const u32* a, const u32* b) {
    asm volatile(
        "mma.sync.aligned.m16n8k16.row.col.f32.f16.f16.f32 "
        "{%0,%1,%2,%3}, {%4,%5,%6,%7}, {%8,%9}, {%0,%1,%2,%3};"
        : "+f"(d[0]), "+f"(d[1]), "+f"(d[2]), "+f"(d[3])
        : "r"(a[0]), "r"(a[1]), "r"(a[2]), "r"(a[3]), "r"(b[0]), "r"(b[1]));
}
__device__ __forceinline__ void split2h(float v0, float v1, u32& hi, u32& lo) {
    __half h0 = __float2half_rn(v0);
    __half h1 = __float2half_rn(v1);
    __half l0 = __float2half_rn(v0 - __half2float(h0));
    __half l1 = __float2half_rn(v1 - __half2float(h1));
    hi = (u32)__half_as_ushort(h0) | ((u32)__half_as_ushort(h1) << 16);
    lo = (u32)__half_as_ushort(l0) | ((u32)__half_as_ushort(l1) << 16);
}
__device__ __forceinline__ u32 pack2h(float v0, float v1) {
    __half h0 = __float2half_rn(v0);
    __half h1 = __float2half_rn(v1);
    return (u32)__half_as_ushort(h0) | ((u32)__half_as_ushort(h1) << 16);
}
__device__ __forceinline__ void cpa16(u32 dst, const void* src) {
    asm volatile("cp.async.cg.shared.global [%0], [%1], 16;"
                 :: "r"(dst), "l"(src));
}
#define CPA_COMMIT() asm volatile("cp.async.commit_group;")
#define CPA_WAIT(n)  asm volatile("cp.async.wait_group %0;" :: "n"(n))

// ---------------- fused convert kernel (x + w1/w2 + mu in one launch) -------
#define XBLOCKS 32768          // BB*CC*NP / 1024
#define WBLOCKS 512            // CC*CC / 512
#define MUBLOCKS 64            // CC*KK / 512
__global__ void kcvt_all(const float* __restrict__ x,
                         const float* __restrict__ w1,
                         const float* __restrict__ w2,
                         const float* __restrict__ mu)
{
    int bx = blockIdx.x;
    if (bx < XBLOCKS) {
        size_t i4 = ((size_t)bx * 256 + threadIdx.x) * 4;
        float4 v = *(const float4*)&x[i4];
        u32 h0, l0, h1, l1;
        split2h(v.x, v.y, h0, l0);
        split2h(v.z, v.w, h1, l1);
        *(uint2*)&g_xh[i4] = make_uint2(h0, h1);
        *(uint2*)&g_xl[i4] = make_uint2(l0, l1);
    } else if (bx < XBLOCKS + WBLOCKS) {
        size_t i2 = ((size_t)(bx - XBLOCKS) * 256 + threadIdx.x) * 2;
        *(u32*)&g_wf1[i2] = pack2h(w1[i2], w1[i2 + 1]);
        *(u32*)&g_wf2[i2] = pack2h(w2[i2], w2[i2 + 1]);
    } else {
        size_t i2 = ((size_t)(bx - XBLOCKS - WBLOCKS) * 256 + threadIdx.x) * 2;
        u32 h, l;
        split2h(mu[i2], mu[i2 + 1], h, l);
        *(u32*)&g_muh[i2] = h; *(u32*)&g_mul[i2] = l;
    }
}

// ---------------- conv GEMM (R13 shape): 128 thr, 64x64 tiles, 4-stage ------
// EPI=0: B = x hi/lo (2-term), bias -> g_xfh/g_xfl fp16 split
// EPI=1: B = rec single fp16 (1-term), BN -> OUT fp32
#define APITCH 40
#define BPITCH 136
#define AH_OFF 0
#define BH_OFF 10240
#define BL_OFF 18944
#define STAGE_B 27648
#define NSTAGE 4
#define NCH 16
#define HCONV_SMEM (STAGE_B * NSTAGE)

template <int EPI>
__global__ __launch_bounds__(128, 2)
void hconv(float* __restrict__ OUT,
           const float* __restrict__ e0, const float* __restrict__ e1,
           const float* __restrict__ e2, const float* __restrict__ e3)
{
    extern __shared__ __align__(16) char dsm[];
    const u32 sb = smem_u32(dsm);

    const int p0 = blockIdx.x * 128;
    const int o0 = blockIdx.y * 128;
    const int b  = blockIdx.z;
    const int tid = threadIdx.x;
    const int lane = tid & 31, wid = tid >> 5;
    const int ob = (wid & 1) * 64, pb = (wid >> 1) * 64;

    const u16* WH = (EPI == 0) ? g_wf1 : g_wf2;
    const u16* IH = ((EPI == 0) ? g_xh : g_rech) + (size_t)b * CC * NP;
    const u16* IL = g_xl + (size_t)b * CC * NP;   // only used when EPI == 0

    float acc[4][8][4];
#pragma unroll
    for (int mf = 0; mf < 4; mf++)
#pragma unroll
        for (int nf = 0; nf < 8; nf++)
#pragma unroll
            for (int q = 0; q < 4; q++) acc[mf][nf][q] = 0.f;

    const int arow = tid >> 2, au = (tid & 3) * 8;
    const int brow = tid >> 4, bu = (tid & 15) * 8;

#define LOAD_CHUNK(st, c0)                                                      \
    do {                                                                        \
        u32 base = sb + (st) * STAGE_B;                                         \
        _Pragma("unroll")                                                       \
        for (int i = 0; i < 4; i++) {                                           \
            int r = arow + i * 32;                                              \
            cpa16(base + AH_OFF + (r * APITCH + au) * 2,                        \
                  WH + (size_t)(o0 + r) * CC + (c0) + au);                      \
        }                                                                       \
        _Pragma("unroll")                                                       \
        for (int i = 0; i < 4; i++) {                                           \
            int r = brow + i * 8;                                               \
            cpa16(base + BH_OFF + (r * BPITCH + bu) * 2,                        \
                  IH + (size_t)((c0) + r) * NP + p0 + bu);                      \
            if (EPI == 0)                                                       \
                cpa16(base + BL_OFF + (r * BPITCH + bu) * 2,                    \
                      IL + (size_t)((c0) + r) * NP + p0 + bu);                  \
        }                                                                       \
        CPA_COMMIT();                                                           \
    } while (0)

    LOAD_CHUNK(0, 0);
    LOAD_CHUNK(1, 32);
    LOAD_CHUNK(2, 64);

    const u32 a_lane = ((ob + (lane & 15)) * APITCH + (lane >> 4) * 8) * 2;
    const u32 b_rbase = (lane & 7) + ((lane >> 3) & 1) * 8;
    const u32 b_col   = pb + ((lane >> 4) & 1) * 8;

    for (int ch = 0; ch < NCH; ch++) {
        if (ch < NCH - 2)      { CPA_WAIT(2); }
        else if (ch == NCH - 2){ CPA_WAIT(1); }
        else                   { CPA_WAIT(0); }
        __syncthreads();
        if (ch < NCH - 3) LOAD_CHUNK((ch + 3) % NSTAGE, (ch + 3) * 32);

        const u32 stb = sb + (ch % NSTAGE) * STAGE_B;
#pragma unroll
        for (int ks = 0; ks < 2; ks++) {
            u32 ah[4][4];
            const u32 abase = stb + a_lane + ks * 32;
#pragma unroll
            for (int mf = 0; mf < 4; mf++)
                ldsm4(ah[mf], abase + AH_OFF + mf * (16 * APITCH * 2));
            const u32 brw = ks * 16 + b_rbase;
            const u32 bbase = stb + (brw * BPITCH + b_col) * 2;
#pragma unroll
            for (int pr = 0; pr < 4; pr++) {
                u32 bh[4], bl[4];
                ldsm4t(bh, bbase + BH_OFF + pr * 32);
                if (EPI == 0) ldsm4t(bl, bbase + BL_OFF + pr * 32);
#pragma unroll
                for (int mf = 0; mf < 4; mf++) {
#pragma unroll
                    for (int hn = 0; hn < 2; hn++) {
                        float* a = acc[mf][pr * 2 + hn];
                        mma_fp16(a, ah[mf], &bh[hn * 2]);
                        if (EPI == 0) mma_fp16(a, ah[mf], &bl[hn * 2]);
                    }
                }
            }
        }
    }

    const int g = lane >> 2, tg = lane & 3;
#pragma unroll
    for (int mf = 0; mf < 4; mf++) {
        int o_lo = o0 + ob + mf * 16 + g;
        int o_hi = o_lo + 8;
        if (EPI == 0) {
            float add_lo = e0[o_lo], add_hi = e0[o_hi];
            u16* xfh = g_xfh + (size_t)b * CC * NP;
            u16* xfl = g_xfl + (size_t)b * CC * NP;
#pragma unroll
            for (int nf = 0; nf < 8; nf++) {
                int pc = p0 + pb + nf * 8 + tg * 2;
                u32 h, l;
                split2h(acc[mf][nf][0] + add_lo, acc[mf][nf][1] + add_lo, h, l);
                *(u32*)&xfh[(size_t)o_lo * NP + pc] = h;
                *(u32*)&xfl[(size_t)o_lo * NP + pc] = l;
                split2h(acc[mf][nf][2] + add_hi, acc[mf][nf][3] + add_hi, h, l);
                *(u32*)&xfh[(size_t)o_hi * NP + pc] = h;
                *(u32*)&xfl[(size_t)o_hi * NP + pc] = l;
            }
        } else {
            float mul_lo = e0[o_lo] * rsqrtf(e3[o_lo] + 1e-5f);
            float add_lo = e1[o_lo] - e2[o_lo] * mul_lo;
            float mul_hi = e0[o_hi] * rsqrtf(e3[o_hi] + 1e-5f);
            float add_hi = e1[o_hi] - e2[o_hi] * mul_hi;
            float* outb = OUT + (size_t)b * CC * NP;
#pragma unroll
            for (int nf = 0; nf < 8; nf++) {
                int pc = p0 + pb + nf * 8 + tg * 2;
                float2 v0, v1;
                v0.x = acc[mf][nf][0] * mul_lo + add_lo;
                v0.y = acc[mf][nf][1] * mul_lo + add_lo;
                v1.x = acc[mf][nf][2] * mul_hi + add_hi;
                v1.y = acc[mf][nf][3] * mul_hi + add_hi;
                *(float2*)&outb[(size_t)o_lo * NP + pc] = v0;
                *(float2*)&outb[(size_t)o_hi * NP + pc] = v1;
            }
        }
    }
#undef LOAD_CHUNK
}

// ---------------- kz: 4 p-warps x 2 k-warps, fp16 3-term --------------------
__global__ __launch_bounds__(256, 2)
void kz_kernel(int use_gm)
{
    __shared__ __align__(16) u16 Xh[32 * 136], Xl[32 * 136]; // (c32, p128)
    __shared__ __align__(16) u16 Mh[32 * 72],  Ml[32 * 72];  // (c32, k64)
    __shared__ float sred[2][128];

    const int p0 = blockIdx.x * 128;
    const int b  = blockIdx.y;
    const int tid = threadIdx.x;
    const int lane = tid & 31, wid = tid >> 5;
    const int pg = wid & 3, kw = wid >> 2;
    const int pwb = pg * 32;

    const u16* XH = g_xfh + (size_t)b * CC * NP;
    const u16* XL = g_xfl + (size_t)b * CC * NP;
    const u16* MH = use_gm ? (g_mh + (size_t)b * CC * KK) : g_muh;
    const u16* ML = use_gm ? (g_ml + (size_t)b * CC * KK) : g_mul;

    float acc[2][4][4];
#pragma unroll
    for (int mf = 0; mf < 2; mf++)
#pragma unroll
        for (int nf = 0; nf < 4; nf++)
#pragma unroll
            for (int q = 0; q < 4; q++) acc[mf][nf][q] = 0.f;

    const u32 sxh = smem_u32(Xh), sxl = smem_u32(Xl);
    const u32 smh = smem_u32(Mh), sml = smem_u32(Ml);

    const int xr0 = tid >> 4,           xg0 = (tid & 15) * 8;
    const int xr1 = (tid + 256) >> 4,   xg1 = (tid & 15) * 8;
    const int mr  = tid >> 3,           mg  = (tid & 7) * 8;

    uint4 pxh[2], pxl[2], pmh, pml;
#define KZ_PREFETCH(c0)                                                        \
    do {                                                                       \
        pxh[0] = *(const uint4*)(XH + (size_t)((c0) + xr0) * NP + p0 + xg0);   \
        pxh[1] = *(const uint4*)(XH + (size_t)((c0) + xr1) * NP + p0 + xg1);   \
        pxl[0] = *(const uint4*)(XL + (size_t)((c0) + xr0) * NP + p0 + xg0);   \
        pxl[1] = *(const uint4*)(XL + (size_t)((c0) + xr1) * NP + p0 + xg1);   \
        pmh    = *(const uint4*)(MH + (size_t)((c0) + mr) * KK + mg);          \
        pml    = *(const uint4*)(ML + (size_t)((c0) + mr) * KK + mg);          \
    } while (0)

    KZ_PREFETCH(0);

    for (int c0 = 0; c0 < CC; c0 += 32) {
        __syncthreads();
        *(uint4*)&Xh[xr0 * 136 + xg0] = pxh[0];
        *(uint4*)&Xh[xr1 * 136 + xg1] = pxh[1];
        *(uint4*)&Xl[xr0 * 136 + xg0] = pxl[0];
        *(uint4*)&Xl[xr1 * 136 + xg1] = pxl[1];
        *(uint4*)&Mh[mr * 72 + mg] = pmh;
        *(uint4*)&Ml[mr * 72 + mg] = pml;
        __syncthreads();
        if (c0 + 32 < CC) KZ_PREFETCH(c0 + 32);

#pragma unroll
        for (int ks = 0; ks < 2; ks++) {
            u32 ah[2][4], al[2][4];
#pragma unroll
            for (int mf = 0; mf < 2; mf++) {
                u32 row = ks * 16 + (lane & 7) + ((lane >> 4) & 1) * 8;
                u32 col = pwb + mf * 16 + ((lane >> 3) & 1) * 8;
                u32 off = (row * 136 + col) << 1;
                ldsm4t(ah[mf], sxh + off);
                ldsm4t(al[mf], sxl + off);
            }
            u32 bh[2][4], bl[2][4];
            {
                u32 row = ks * 16 + (lane & 7) + ((lane >> 3) & 1) * 8;
                u32 col = kw * 32 + ((lane >> 4) & 1) * 8;
#pragma unroll
                for (int pr = 0; pr < 2; pr++) {
                    u32 off = (row * 72 + col + pr * 16) << 1;
                    ldsm4t(bh[pr], smh + off);
                    ldsm4t(bl[pr], sml + off);
                }
            }
#pragma unroll
            for (int mf = 0; mf < 2; mf++)
#pragma unroll
                for (int nf = 0; nf < 4; nf++) {
                    const u32* bhp = &bh[nf >> 1][(nf & 1) * 2];
                    const u32* blp = &bl[nf >> 1][(nf & 1) * 2];
                    mma_fp16(acc[mf][nf], ah[mf], bhp);
                    mma_fp16(acc[mf][nf], ah[mf], blp);
                    mma_fp16(acc[mf][nf], al[mf], bhp);
                }
        }
    }
#undef KZ_PREFETCH

    // ---- softmax over k=64 split across 2 k-warps ----
    const int gr = lane >> 2, tg = lane & 3;
    float pm[2][2];
#pragma unroll
    for (int mf = 0; mf < 2; mf++) {
        float m0 = -1e30f, m1 = -1e30f;
#pragma unroll
        for (int nf = 0; nf < 4; nf++) {
            m0 = fmaxf(m0, fmaxf(acc[mf][nf][0], acc[mf][nf][1]));
            m1 = fmaxf(m1, fmaxf(acc[mf][nf][2], acc[mf][nf][3]));
        }
#pragma unroll
        for (int s = 1; s < 4; s <<= 1) {
            m0 = fmaxf(m0, __shfl_xor_sync(0xffffffffu, m0, s));
            m1 = fmaxf(m1, __shfl_xor_sync(0xffffffffu, m1, s));
        }
        pm[mf][0] = m0; pm[mf][1] = m1;
    }
    if (tg == 0) {
#pragma unroll
        for (int mf = 0; mf < 2; mf++) {
            sred[kw][pwb + mf * 16 + gr]     = pm[mf][0];
            sred[kw][pwb + mf * 16 + gr + 8] = pm[mf][1];
        }
    }
    __syncthreads();
    float fm[2][2];
#pragma unroll
    for (int mf = 0; mf < 2; mf++) {
        fm[mf][0] = fmaxf(pm[mf][0], sred[kw ^ 1][pwb + mf * 16 + gr]);
        fm[mf][1] = fmaxf(pm[mf][1], sred[kw ^ 1][pwb + mf * 16 + gr + 8]);
    }
    __syncthreads();
    float ps[2][2];
#pragma unroll
    for (int mf = 0; mf < 2; mf++) {
        float s0 = 0.f, s1 = 0.f;
#pragma unroll
        for (int nf = 0; nf < 4; nf++) {
            acc[mf][nf][0] = expf(acc[mf][nf][0] - fm[mf][0]); s0 += acc[mf][nf][0];
            acc[mf][nf][1] = expf(acc[mf][nf][1] - fm[mf][0]); s0 += acc[mf][nf][1];
            acc[mf][nf][2] = expf(acc[mf][nf][2] - fm[mf][1]); s1 += acc[mf][nf][2];
            acc[mf][nf][3] = expf(acc[mf][nf][3] - fm[mf][1]); s1 += acc[mf][nf][3];
        }
#pragma unroll
        for (int s = 1; s < 4; s <<= 1) {
            s0 += __shfl_xor_sync(0xffffffffu, s0, s);
            s1 += __shfl_xor_sync(0xffffffffu, s1, s);
        }
        ps[mf][0] = s0; ps[mf][1] = s1;
    }
    if (tg == 0) {
#pragma unroll
        for (int mf = 0; mf < 2; mf++) {
            sred[kw][pwb + mf * 16 + gr]     = ps[mf][0];
            sred[kw][pwb + mf * 16 + gr + 8] = ps[mf][1];
        }
    }
    __syncthreads();
#pragma unroll
    for (int mf = 0; mf < 2; mf++) {
        float inv0 = 1.f / (ps[mf][0] + sred[kw ^ 1][pwb + mf * 16 + gr]);
        float inv1 = 1.f / (ps[mf][1] + sred[kw ^ 1][pwb + mf * 16 + gr + 8]);
        size_t prow_lo = (size_t)(b * NP + p0 + pwb + mf * 16 + gr) * KK;
        size_t prow_hi = prow_lo + (size_t)8 * KK;
#pragma unroll
        for (int nf = 0; nf < 4; nf++) {
            int kc = kw * 32 + nf * 8 + tg * 2;
            u32 h, l;
            split2h(acc[mf][nf][0] * inv0, acc[mf][nf][1] * inv0, h, l);
            *(u32*)&g_zh[prow_lo + kc] = h;
            *(u32*)&g_zl[prow_lo + kc] = l;
            split2h(acc[mf][nf][2] * inv1, acc[mf][nf][3] * inv1, h, l);
            *(u32*)&g_zh[prow_hi + kc] = h;
            *(u32*)&g_zl[prow_hi + kc] = l;
        }
    }
}

// ---------------- km: 4 c-warps x 2 k-warps, fp16 3-term --------------------
__global__ __launch_bounds__(256, 2)
void km_kernel()
{
    __shared__ __align__(16) u16 Ah[128 * 40], Al[128 * 40]; // (c128, p32)
    __shared__ __align__(16) u16 Zh[32 * 72],  Zl[32 * 72];  // (p32, k64)

    const int ct0 = blockIdx.x * 128;
    const int b   = blockIdx.y;
    const int s   = blockIdx.z;
    const int ps0 = s * (NP / NSPLIT);
    const int tid = threadIdx.x;
    const int lane = tid & 31, wid = tid >> 5;
    const int cw = wid & 3, kw = wid >> 2;

    const u16* XH = g_xfh + (size_t)b * CC * NP;
    const u16* XL = g_xfl + (size_t)b * CC * NP;
    const u16* ZH = g_zh + (size_t)b * NP * KK;
    const u16* ZL = g_zl + (size_t)b * NP * KK;

    float acc[2][4][4];
#pragma unroll
    for (int mf = 0; mf < 2; mf++)
#pragma unroll
        for (int nf = 0; nf < 4; nf++)
#pragma unroll
            for (int q = 0; q < 4; q++) acc[mf][nf][q] = 0.f;

    const u32 sah = smem_u32(Ah), sal = smem_u32(Al);
    const u32 szh = smem_u32(Zh), szl = smem_u32(Zl);

    const int ar0 = tid >> 2,         ag0 = (tid & 3) * 8;
    const int ar1 = (tid + 256) >> 2, ag1 = (tid & 3) * 8;
    const int zr  = tid >> 3,         zg  = (tid & 7) * 8;

    uint4 pah[2], pal[2], pzh, pzl;
#define KM_PREFETCH(pc0)                                                       \
    do {                                                                       \
        pah[0] = *(const uint4*)(XH + (size_t)(ct0 + ar0) * NP + (pc0) + ag0); \
        pah[1] = *(const uint4*)(XH + (size_t)(ct0 + ar1) * NP + (pc0) + ag1); \
        pal[0] = *(const uint4*)(XL + (size_t)(ct0 + ar0) * NP + (pc0) + ag0); \
        pal[1] = *(const uint4*)(XL + (size_t)(ct0 + ar1) * NP + (pc0) + ag1); \
        pzh    = *(const uint4*)(ZH + (size_t)((pc0) + zr) * KK + zg);         \
        pzl    = *(const uint4*)(ZL + (size_t)((pc0) + zr) * KK + zg);         \
    } while (0)

    KM_PREFETCH(ps0);

    for (int pc0 = ps0; pc0 < ps0 + NP / NSPLIT; pc0 += 32) {
        __syncthreads();
        *(uint4*)&Ah[ar0 * 40 + ag0] = pah[0];
        *(uint4*)&Ah[ar1 * 40 + ag1] = pah[1];
        *(uint4*)&Al[ar0 * 40 + ag0] = pal[0];
        *(uint4*)&Al[ar1 * 40 + ag1] = pal[1];
        *(uint4*)&Zh[zr * 72 + zg] = pzh;
        *(uint4*)&Zl[zr * 72 + zg] = pzl;
        __syncthreads();
        if (pc0 + 32 < ps0 + NP / NSPLIT) KM_PREFETCH(pc0 + 32);

#pragma unroll
        for (int ks = 0; ks < 2; ks++) {
            u32 ah[2][4], al[2][4];
#pragma unroll
            for (int mf = 0; mf < 2; mf++) {
                u32 off = (((cw * 32 + mf * 16 + (lane & 15)) * 40 +
                            ks * 16 + (lane >> 4) * 8)) << 1;
                ldsm4(ah[mf], sah + off);
                ldsm4(al[mf], sal + off);
            }
            u32 bh[2][4], bl[2][4];
            {
                u32 row = ks * 16 + (lane & 7) + ((lane >> 3) & 1) * 8;
                u32 col = kw * 32 + ((lane >> 4) & 1) * 8;
#pragma unroll
                for (int pr = 0; pr < 2; pr++) {
                    u32 off = (row * 72 + col + pr * 16) << 1;
                    ldsm4t(bh[pr], szh + off);
                    ldsm4t(bl[pr], szl + off);
                }
            }
#pragma unroll
            for (int mf = 0; mf < 2; mf++)
#pragma unroll
                for (int nf = 0; nf < 4; nf++) {
                    const u32* bhp = &bh[nf >> 1][(nf & 1) * 2];
                    const u32* blp = &bl[nf >> 1][(nf & 1) * 2];
                    mma_fp16(acc[mf][nf], ah[mf], bhp);
                    mma_fp16(acc[mf][nf], ah[mf], blp);
                    mma_fp16(acc[mf][nf], al[mf], bhp);
                }
        }
    }
#undef KM_PREFETCH

    const int gr = lane >> 2, tg = lane & 3;
    float* out = g_mpart + ((size_t)(s * BB + b) * CC + ct0 + cw * 32) * KK;
#pragma unroll
    for (int mf = 0; mf < 2; mf++)
#pragma unroll
        for (int nf = 0; nf < 4; nf++) {
            int kc = kw * 32 + nf * 8 + tg * 2;
            int r0 = mf * 16 + gr;
            *(float2*)&out[(size_t)r0 * KK + kc] =
                make_float2(acc[mf][nf][0], acc[mf][nf][1]);
            *(float2*)&out[(size_t)(r0 + 8) * KK + kc] =
                make_float2(acc[mf][nf][2], acc[mf][nf][3]);
        }
}

// ---------------- fused norm: grid (4, BB), emits fp16 hi/lo ----------------
__global__ __launch_bounds__(1024)
void knorm_fused()
{
    const int b  = blockIdx.y;
    const int k0 = blockIdx.x * 16;
    const int tid = threadIdx.x;
    const int kl = tid & 15;
    const int cg = tid >> 4;            // 0..63, each owns 8 c-rows

    __shared__ float red[64][17];

    const size_t base = (size_t)b * CC * KK;
    const int k = k0 + kl;
    float v[8];
    float ss = 0.f;
#pragma unroll
    for (int i = 0; i < 8; i++) {
        size_t off = base + (size_t)(cg * 8 + i) * KK + k;
        float t = 0.f;
#pragma unroll
        for (int s = 0; s < NSPLIT; s++)
            t += g_mpart[(size_t)s * (BB * CC * KK) + off];
        v[i] = t;
        ss += t * t;
    }
    red[cg][kl] = ss;
    __syncthreads();
#pragma unroll
    for (int s = 32; s > 0; s >>= 1) {
        if (cg < s) red[cg][kl] += red[cg + s][kl];
        __syncthreads();
    }
    const float inv = 1.f / (EPSF + sqrtf(red[0][kl]));
    u16* mh = g_mh + base;
    u16* ml = g_ml + base;
#pragma unroll
    for (int i = 0; i < 8; i++) {
        float sv = v[i] * inv;
        __half h = __float2half_rn(sv);
        __half l = __float2half_rn(sv - __half2float(h));
        size_t off = (size_t)(cg * 8 + i) * KK + k;
        mh[off] = __half_as_ushort(h);
        ml[off] = __half_as_ushort(l);
    }
}

// ---------------- krec: rec = relu(m @ z^T), m single fp16, 2-term ----------
__global__ __launch_bounds__(256, 2)
void krec_kernel()
{
    __shared__ __align__(16) u16 Ah[128 * 40];               // (c128, k32) m hi
    __shared__ __align__(16) u16 Bh[128 * 40], Bl[128 * 40]; // (p128, k32)

    const int p0  = blockIdx.x * 128;
    const int ct0 = blockIdx.y * 128;
    const int b   = blockIdx.z;
    const int tid = threadIdx.x;
    const int lane = tid & 31, wid = tid >> 5;
    const int wm = wid & 1, wn = wid >> 1;
    const int cb = wm * 64, pb = wn * 32;

    const u16* MH = g_mh + (size_t)b * CC * KK;
    const u16* ZH = g_zh + (size_t)b * NP * KK;
    const u16* ZL = g_zl + (size_t)b * NP * KK;

    float acc[4][4][4];
#pragma unroll
    for (int mf = 0; mf < 4; mf++)
#pragma unroll
        for (int nf = 0; nf < 4; nf++)
#pragma unroll
            for (int q = 0; q < 4; q++) acc[mf][nf][q] = 0.f;

    const u32 sah = smem_u32(Ah);
    const u32 sbh = smem_u32(Bh), sbl = smem_u32(Bl);

    for (int kc0 = 0; kc0 < KK; kc0 += 32) {
#pragma unroll
        for (int it = 0; it < 2; it++) {
            int lin = tid + it * 256;
            int r = lin >> 2, g = lin & 3;
            *(uint4*)&Ah[r * 40 + g * 8] =
                *(const uint4*)(MH + (size_t)(ct0 + r) * KK + kc0 + g * 8);
        }
#pragma unroll
        for (int it = 0; it < 2; it++) {
            int lin = tid + it * 256;
            int r = lin >> 2, g = lin & 3;
            *(uint4*)&Bh[r * 40 + g * 8] =
                *(const uint4*)(ZH + (size_t)(p0 + r) * KK + kc0 + g * 8);
            *(uint4*)&Bl[r * 40 + g * 8] =
                *(const uint4*)(ZL + (size_t)(p0 + r) * KK + kc0 + g * 8);
        }
        __syncthreads();
#pragma unroll
        for (int ks = 0; ks < 2; ks++) {
            u32 ah[4][4];
            u32 a_off = (((cb + (lane & 15)) * 40 + ks * 16 + (lane >> 4) * 8)) << 1;
#pragma unroll
            for (int mf = 0; mf < 4; mf++)
                ldsm4(ah[mf], sah + a_off + mf * (16 * 40 * 2));
            u32 bh[2][4], bl[2][4];
            u32 brow = pb + ((lane >> 4) & 1) * 8 + (lane & 7);
            u32 bcol = ks * 16 + ((lane >> 3) & 1) * 8;
#pragma unroll
            for (int pr = 0; pr < 2; pr++) {
                u32 boff = ((brow + pr * 16) * 40 + bcol) << 1;
                ldsm4(bh[pr], sbh + boff);
                ldsm4(bl[pr], sbl + boff);
            }
#pragma unroll
            for (int mf = 0; mf < 4; mf++)
#pragma unroll
                for (int nf = 0; nf < 4; nf++) {
                    const u32* bhp = &bh[nf >> 1][(nf & 1) * 2];
                    const u32* blp = &bl[nf >> 1][(nf & 1) * 2];
                    mma_fp16(acc[mf][nf], ah[mf], bhp);
                    mma_fp16(acc[mf][nf], ah[mf], blp);
                }
        }
        __syncthreads();
    }

    const int g = lane >> 2, tg = lane & 3;
    u16* rh = g_rech + (size_t)b * CC * NP;
#pragma unroll
    for (int mf = 0; mf < 4; mf++) {
        int c_lo = ct0 + cb + mf * 16 + g;
        int c_hi = c_lo + 8;
#pragma unroll
        for (int nf = 0; nf < 4; nf++) {
            int pc = p0 + pb + nf * 8 + tg * 2;
            *(u32*)&rh[(size_t)c_lo * NP + pc] =
                pack2h(fmaxf(acc[mf][nf][0], 0.f), fmaxf(acc[mf][nf][1], 0.f));
            *(u32*)&rh[(size_t)c_hi * NP + pc] =
                pack2h(fmaxf(acc[mf][nf][2], 0.f), fmaxf(acc[mf][nf][3], 0.f));
        }
    }
}

// ---------------- launch ----------------------------------------------------
extern "C" void kernel_launch(void* const* d_in, const int* in_sizes, int n_in,
                              void* d_out, int out_size)
{
    (void)in_sizes; (void)n_in; (void)out_size;
    const float* x     = (const float*)d_in[0];
    const float* w1    = (const float*)d_in[1];
    const float* b1    = (const float*)d_in[2];
    const float* mu    = (const float*)d_in[3];
    const float* w2    = (const float*)d_in[4];
    const float* gamma = (const float*)d_in[5];
    const float* beta  = (const float*)d_in[6];
    const float* mean  = (const float*)d_in[7];
    const float* var   = (const float*)d_in[8];
    float* out = (float*)d_out;

    cudaFuncSetAttribute(hconv<0>, cudaFuncAttributeMaxDynamicSharedMemorySize,
                         HCONV_SMEM);
    cudaFuncSetAttribute(hconv<1>, cudaFuncAttributeMaxDynamicSharedMemorySize,
                         HCONV_SMEM);

    kcvt_all<<<XBLOCKS + WBLOCKS + MUBLOCKS, 256>>>(x, w1, w2, mu);

    hconv<0><<<dim3(NP / 128, CC / 128, BB), 128, HCONV_SMEM>>>(
        nullptr, b1, nullptr, nullptr, nullptr);

    for (int st = 0; st < 3; st++) {
        kz_kernel<<<dim3(NP / 128, BB), 256>>>(st > 0 ? 1 : 0);
        km_kernel<<<dim3(CC / 128, BB, NSPLIT), 256>>>();
        knorm_fused<<<dim3(4, BB), 1024>>>();
    }

    krec_kernel<<<dim3(NP / 128, CC / 128, BB), 256>>>();

    hconv<1><<<dim3(NP / 128, CC / 128, BB), 128, HCONV_SMEM>>>(
        out, gamma, beta, mean, var);
}

// round 16
// speedup vs baseline: 1.1851x; 1.1429x over previous
#include <cuda_runtime.h>
#include <cuda_bf16.h>
#include <cuda_fp16.h>

#define CC 512
#define NP 4096
#define KK 64
#define BB 16
#define NSPLIT 4
#define EPSF 1e-6f

typedef unsigned long long u64;
typedef unsigned int u32;
typedef unsigned short u16;

// ---------------- scratch (static device globals) ---------------------------
__device__ u16 g_xh[(size_t)BB * CC * NP];   // x hi fp16 (b,c,p)
__device__ u16 g_xl[(size_t)BB * CC * NP];   // x lo fp16
__device__ u16 g_wf1[(size_t)CC * CC];       // w1 fp16 single
__device__ u16 g_wf2[(size_t)CC * CC];       // w2 fp16 single
__device__ u16 g_muh[(size_t)CC * KK], g_mul[(size_t)CC * KK];   // fp16 hi/lo
__device__ u16 g_xf[(size_t)BB * CC * NP];   // conv1 out SINGLE fp16 (b,c,p)
__device__ u16 g_zh[(size_t)BB * NP * KK];   // z hi fp16 (b,p,k)
__device__ u16 g_zl[(size_t)BB * NP * KK];
__device__ u16 g_mh[(size_t)BB * CC * KK];   // m hi fp16 (b,c,k)
__device__ u16 g_ml[(size_t)BB * CC * KK];
__device__ u16 g_rech[(size_t)BB * CC * NP]; // relu(rec) fp16 single (b,c,p)
__device__ float g_mpart[(size_t)NSPLIT * BB * CC * KK];

// ---------------- helpers ----------------------------------------------------
__device__ __forceinline__ u32 smem_u32(const void* p) {
    u32 a;
    asm("{ .reg .u64 t; cvta.to.shared.u64 t, %1; cvt.u32.u64 %0, t; }"
        : "=r"(a) : "l"(p));
    return a;
}
__device__ __forceinline__ void ldsm4(u32* r, u32 addr) {
    asm volatile("ldmatrix.sync.aligned.m8n8.x4.shared.b16 {%0,%1,%2,%3}, [%4];"
                 : "=r"(r[0]), "=r"(r[1]), "=r"(r[2]), "=r"(r[3]) : "r"(addr));
}
__device__ __forceinline__ void ldsm4t(u32* r, u32 addr) {
    asm volatile("ldmatrix.sync.aligned.m8n8.x4.trans.shared.b16 {%0,%1,%2,%3}, [%4];"
                 : "=r"(r[0]), "=r"(r[1]), "=r"(r[2]), "=r"(r[3]) : "r"(addr));
}
__device__ __forceinline__ void mma_fp16(float* d, const u32* a, const u32* b) {
    asm volatile(
        "mma.sync.aligned.m16n8k16.row.col.f32.f16.f16.f32 "
        "{%0,%1,%2,%3}, {%4,%5,%6,%7}, {%8,%9}, {%0,%1,%2,%3};"
        : "+f"(d[0]), "+f"(d[1]), "+f"(d[2]), "+f"(d[3])
        : "r"(a[0]), "r"(a[1]), "r"(a[2]), "r"(a[3]), "r"(b[0]), "r"(b[1]));
}
__device__ __forceinline__ void split2h(float v0, float v1, u32& hi, u32& lo) {
    __half h0 = __float2half_rn(v0);
    __half h1 = __float2half_rn(v1);
    __half l0 = __float2half_rn(v0 - __half2float(h0));
    __half l1 = __float2half_rn(v1 - __half2float(h1));
    hi = (u32)__half_as_ushort(h0) | ((u32)__half_as_ushort(h1) << 16);
    lo = (u32)__half_as_ushort(l0) | ((u32)__half_as_ushort(l1) << 16);
}
__device__ __forceinline__ u32 pack2h(float v0, float v1) {
    __half h0 = __float2half_rn(v0);
    __half h1 = __float2half_rn(v1);
    return (u32)__half_as_ushort(h0) | ((u32)__half_as_ushort(h1) << 16);
}
__device__ __forceinline__ void cpa16(u32 dst, const void* src) {
    asm volatile("cp.async.cg.shared.global [%0], [%1], 16;"
                 :: "r"(dst), "l"(src));
}
#define CPA_COMMIT() asm volatile("cp.async.commit_group;")
#define CPA_WAIT(n)  asm volatile("cp.async.wait_group %0;" :: "n"(n))

// ---------------- fused convert kernel (x + w1/w2 + mu in one launch) -------
#define XBLOCKS 32768          // BB*CC*NP / 1024
#define WBLOCKS 512            // CC*CC / 512
#define MUBLOCKS 64            // CC*KK / 512
__global__ void kcvt_all(const float* __restrict__ x,
                         const float* __restrict__ w1,
                         const float* __restrict__ w2,
                         const float* __restrict__ mu)
{
    int bx = blockIdx.x;
    if (bx < XBLOCKS) {
        size_t i4 = ((size_t)bx * 256 + threadIdx.x) * 4;
        float4 v = *(const float4*)&x[i4];
        u32 h0, l0, h1, l1;
        split2h(v.x, v.y, h0, l0);
        split2h(v.z, v.w, h1, l1);
        *(uint2*)&g_xh[i4] = make_uint2(h0, h1);
        *(uint2*)&g_xl[i4] = make_uint2(l0, l1);
    } else if (bx < XBLOCKS + WBLOCKS) {
        size_t i2 = ((size_t)(bx - XBLOCKS) * 256 + threadIdx.x) * 2;
        *(u32*)&g_wf1[i2] = pack2h(w1[i2], w1[i2 + 1]);
        *(u32*)&g_wf2[i2] = pack2h(w2[i2], w2[i2 + 1]);
    } else {
        size_t i2 = ((size_t)(bx - XBLOCKS - WBLOCKS) * 256 + threadIdx.x) * 2;
        u32 h, l;
        split2h(mu[i2], mu[i2 + 1], h, l);
        *(u32*)&g_muh[i2] = h; *(u32*)&g_mul[i2] = l;
    }
}

// ---------------- conv GEMM: 128 thr, 64x64 tiles, 4-stage ------------------
// EPI=0: B = x hi/lo (2-term), bias -> g_xf single fp16
// EPI=1: B = rec single fp16 (1-term), BN -> OUT fp32
#define APITCH 40
#define BPITCH 136
#define AH_OFF 0
#define BH_OFF 10240
#define BL_OFF 18944
#define STAGE_B 27648
#define NSTAGE 4
#define NCH 16
#define HCONV_SMEM (STAGE_B * NSTAGE)

template <int EPI>
__global__ __launch_bounds__(128, 2)
void hconv(float* __restrict__ OUT,
           const float* __restrict__ e0, const float* __restrict__ e1,
           const float* __restrict__ e2, const float* __restrict__ e3)
{
    extern __shared__ __align__(16) char dsm[];
    const u32 sb = smem_u32(dsm);

    const int p0 = blockIdx.x * 128;
    const int o0 = blockIdx.y * 128;
    const int b  = blockIdx.z;
    const int tid = threadIdx.x;
    const int lane = tid & 31, wid = tid >> 5;
    const int ob = (wid & 1) * 64, pb = (wid >> 1) * 64;

    const u16* WH = (EPI == 0) ? g_wf1 : g_wf2;
    const u16* IH = ((EPI == 0) ? g_xh : g_rech) + (size_t)b * CC * NP;
    const u16* IL = g_xl + (size_t)b * CC * NP;   // only used when EPI == 0

    float acc[4][8][4];
#pragma unroll
    for (int mf = 0; mf < 4; mf++)
#pragma unroll
        for (int nf = 0; nf < 8; nf++)
#pragma unroll
            for (int q = 0; q < 4; q++) acc[mf][nf][q] = 0.f;

    const int arow = tid >> 2, au = (tid & 3) * 8;
    const int brow = tid >> 4, bu = (tid & 15) * 8;

#define LOAD_CHUNK(st, c0)                                                      \
    do {                                                                        \
        u32 base = sb + (st) * STAGE_B;                                         \
        _Pragma("unroll")                                                       \
        for (int i = 0; i < 4; i++) {                                           \
            int r = arow + i * 32;                                              \
            cpa16(base + AH_OFF + (r * APITCH + au) * 2,                        \
                  WH + (size_t)(o0 + r) * CC + (c0) + au);                      \
        }                                                                       \
        _Pragma("unroll")                                                       \
        for (int i = 0; i < 4; i++) {                                           \
            int r = brow + i * 8;                                               \
            cpa16(base + BH_OFF + (r * BPITCH + bu) * 2,                        \
                  IH + (size_t)((c0) + r) * NP + p0 + bu);                      \
            if (EPI == 0)                                                       \
                cpa16(base + BL_OFF + (r * BPITCH + bu) * 2,                    \
                      IL + (size_t)((c0) + r) * NP + p0 + bu);                  \
        }                                                                       \
        CPA_COMMIT();                                                           \
    } while (0)

    LOAD_CHUNK(0, 0);
    LOAD_CHUNK(1, 32);
    LOAD_CHUNK(2, 64);

    const u32 a_lane = ((ob + (lane & 15)) * APITCH + (lane >> 4) * 8) * 2;
    const u32 b_rbase = (lane & 7) + ((lane >> 3) & 1) * 8;
    const u32 b_col   = pb + ((lane >> 4) & 1) * 8;

    for (int ch = 0; ch < NCH; ch++) {
        if (ch < NCH - 2)      { CPA_WAIT(2); }
        else if (ch == NCH - 2){ CPA_WAIT(1); }
        else                   { CPA_WAIT(0); }
        __syncthreads();
        if (ch < NCH - 3) LOAD_CHUNK((ch + 3) % NSTAGE, (ch + 3) * 32);

        const u32 stb = sb + (ch % NSTAGE) * STAGE_B;
#pragma unroll
        for (int ks = 0; ks < 2; ks++) {
            u32 ah[4][4];
            const u32 abase = stb + a_lane + ks * 32;
#pragma unroll
            for (int mf = 0; mf < 4; mf++)
                ldsm4(ah[mf], abase + AH_OFF + mf * (16 * APITCH * 2));
            const u32 brw = ks * 16 + b_rbase;
            const u32 bbase = stb + (brw * BPITCH + b_col) * 2;
#pragma unroll
            for (int pr = 0; pr < 4; pr++) {
                u32 bh[4], bl[4];
                ldsm4t(bh, bbase + BH_OFF + pr * 32);
                if (EPI == 0) ldsm4t(bl, bbase + BL_OFF + pr * 32);
#pragma unroll
                for (int mf = 0; mf < 4; mf++) {
#pragma unroll
                    for (int hn = 0; hn < 2; hn++) {
                        float* a = acc[mf][pr * 2 + hn];
                        mma_fp16(a, ah[mf], &bh[hn * 2]);
                        if (EPI == 0) mma_fp16(a, ah[mf], &bl[hn * 2]);
                    }
                }
            }
        }
    }

    const int g = lane >> 2, tg = lane & 3;
#pragma unroll
    for (int mf = 0; mf < 4; mf++) {
        int o_lo = o0 + ob + mf * 16 + g;
        int o_hi = o_lo + 8;
        if (EPI == 0) {
            float add_lo = e0[o_lo], add_hi = e0[o_hi];
            u16* xf = g_xf + (size_t)b * CC * NP;
#pragma unroll
            for (int nf = 0; nf < 8; nf++) {
                int pc = p0 + pb + nf * 8 + tg * 2;
                *(u32*)&xf[(size_t)o_lo * NP + pc] =
                    pack2h(acc[mf][nf][0] + add_lo, acc[mf][nf][1] + add_lo);
                *(u32*)&xf[(size_t)o_hi * NP + pc] =
                    pack2h(acc[mf][nf][2] + add_hi, acc[mf][nf][3] + add_hi);
            }
        } else {
            float mul_lo = e0[o_lo] * rsqrtf(e3[o_lo] + 1e-5f);
            float add_lo = e1[o_lo] - e2[o_lo] * mul_lo;
            float mul_hi = e0[o_hi] * rsqrtf(e3[o_hi] + 1e-5f);
            float add_hi = e1[o_hi] - e2[o_hi] * mul_hi;
            float* outb = OUT + (size_t)b * CC * NP;
#pragma unroll
            for (int nf = 0; nf < 8; nf++) {
                int pc = p0 + pb + nf * 8 + tg * 2;
                float2 v0, v1;
                v0.x = acc[mf][nf][0] * mul_lo + add_lo;
                v0.y = acc[mf][nf][1] * mul_lo + add_lo;
                v1.x = acc[mf][nf][2] * mul_hi + add_hi;
                v1.y = acc[mf][nf][3] * mul_hi + add_hi;
                *(float2*)&outb[(size_t)o_lo * NP + pc] = v0;
                *(float2*)&outb[(size_t)o_hi * NP + pc] = v1;
            }
        }
    }
#undef LOAD_CHUNK
}

// ---------------- kz: xf single fp16, m hi/lo -> 2-term ----------------------
__global__ __launch_bounds__(256, 2)
void kz_kernel(int use_gm)
{
    __shared__ __align__(16) u16 Xs[32 * 136];               // (c32, p128)
    __shared__ __align__(16) u16 Mh[32 * 72],  Ml[32 * 72];  // (c32, k64)
    __shared__ float sred[2][128];

    const int p0 = blockIdx.x * 128;
    const int b  = blockIdx.y;
    const int tid = threadIdx.x;
    const int lane = tid & 31, wid = tid >> 5;
    const int pg = wid & 3, kw = wid >> 2;
    const int pwb = pg * 32;

    const u16* XF = g_xf + (size_t)b * CC * NP;
    const u16* MH = use_gm ? (g_mh + (size_t)b * CC * KK) : g_muh;
    const u16* ML = use_gm ? (g_ml + (size_t)b * CC * KK) : g_mul;

    float acc[2][4][4];
#pragma unroll
    for (int mf = 0; mf < 2; mf++)
#pragma unroll
        for (int nf = 0; nf < 4; nf++)
#pragma unroll
            for (int q = 0; q < 4; q++) acc[mf][nf][q] = 0.f;

    const u32 sx = smem_u32(Xs);
    const u32 smh = smem_u32(Mh), sml = smem_u32(Ml);

    const int xr0 = tid >> 4,           xg0 = (tid & 15) * 8;
    const int xr1 = (tid + 256) >> 4,   xg1 = (tid & 15) * 8;
    const int mr  = tid >> 3,           mg  = (tid & 7) * 8;

    uint4 px[2], pmh, pml;
#define KZ_PREFETCH(c0)                                                        \
    do {                                                                       \
        px[0] = *(const uint4*)(XF + (size_t)((c0) + xr0) * NP + p0 + xg0);    \
        px[1] = *(const uint4*)(XF + (size_t)((c0) + xr1) * NP + p0 + xg1);    \
        pmh   = *(const uint4*)(MH + (size_t)((c0) + mr) * KK + mg);           \
        pml   = *(const uint4*)(ML + (size_t)((c0) + mr) * KK + mg);           \
    } while (0)

    KZ_PREFETCH(0);

    for (int c0 = 0; c0 < CC; c0 += 32) {
        __syncthreads();
        *(uint4*)&Xs[xr0 * 136 + xg0] = px[0];
        *(uint4*)&Xs[xr1 * 136 + xg1] = px[1];
        *(uint4*)&Mh[mr * 72 + mg] = pmh;
        *(uint4*)&Ml[mr * 72 + mg] = pml;
        __syncthreads();
        if (c0 + 32 < CC) KZ_PREFETCH(c0 + 32);

#pragma unroll
        for (int ks = 0; ks < 2; ks++) {
            u32 ah[2][4];
#pragma unroll
            for (int mf = 0; mf < 2; mf++) {
                u32 row = ks * 16 + (lane & 7) + ((lane >> 4) & 1) * 8;
                u32 col = pwb + mf * 16 + ((lane >> 3) & 1) * 8;
                u32 off = (row * 136 + col) << 1;
                ldsm4t(ah[mf], sx + off);
            }
            u32 bh[2][4], bl[2][4];
            {
                u32 row = ks * 16 + (lane & 7) + ((lane >> 3) & 1) * 8;
                u32 col = kw * 32 + ((lane >> 4) & 1) * 8;
#pragma unroll
                for (int pr = 0; pr < 2; pr++) {
                    u32 off = (row * 72 + col + pr * 16) << 1;
                    ldsm4t(bh[pr], smh + off);
                    ldsm4t(bl[pr], sml + off);
                }
            }
#pragma unroll
            for (int mf = 0; mf < 2; mf++)
#pragma unroll
                for (int nf = 0; nf < 4; nf++) {
                    const u32* bhp = &bh[nf >> 1][(nf & 1) * 2];
                    const u32* blp = &bl[nf >> 1][(nf & 1) * 2];
                    mma_fp16(acc[mf][nf], ah[mf], bhp);
                    mma_fp16(acc[mf][nf], ah[mf], blp);
                }
        }
    }
#undef KZ_PREFETCH

    // ---- softmax over k=64 split across 2 k-warps ----
    const int gr = lane >> 2, tg = lane & 3;
    float pm[2][2];
#pragma unroll
    for (int mf = 0; mf < 2; mf++) {
        float m0 = -1e30f, m1 = -1e30f;
#pragma unroll
        for (int nf = 0; nf < 4; nf++) {
            m0 = fmaxf(m0, fmaxf(acc[mf][nf][0], acc[mf][nf][1]));
            m1 = fmaxf(m1, fmaxf(acc[mf][nf][2], acc[mf][nf][3]));
        }
#pragma unroll
        for (int s = 1; s < 4; s <<= 1) {
            m0 = fmaxf(m0, __shfl_xor_sync(0xffffffffu, m0, s));
            m1 = fmaxf(m1, __shfl_xor_sync(0xffffffffu, m1, s));
        }
        pm[mf][0] = m0; pm[mf][1] = m1;
    }
    if (tg == 0) {
#pragma unroll
        for (int mf = 0; mf < 2; mf++) {
            sred[kw][pwb + mf * 16 + gr]     = pm[mf][0];
            sred[kw][pwb + mf * 16 + gr + 8] = pm[mf][1];
        }
    }
    __syncthreads();
    float fm[2][2];
#pragma unroll
    for (int mf = 0; mf < 2; mf++) {
        fm[mf][0] = fmaxf(pm[mf][0], sred[kw ^ 1][pwb + mf * 16 + gr]);
        fm[mf][1] = fmaxf(pm[mf][1], sred[kw ^ 1][pwb + mf * 16 + gr + 8]);
    }
    __syncthreads();
    float ps[2][2];
#pragma unroll
    for (int mf = 0; mf < 2; mf++) {
        float s0 = 0.f, s1 = 0.f;
#pragma unroll
        for (int nf = 0; nf < 4; nf++) {
            acc[mf][nf][0] = expf(acc[mf][nf][0] - fm[mf][0]); s0 += acc[mf][nf][0];
            acc[mf][nf][1] = expf(acc[mf][nf][1] - fm[mf][0]); s0 += acc[mf][nf][1];
            acc[mf][nf][2] = expf(acc[mf][nf][2] - fm[mf][1]); s1 += acc[mf][nf][2];
            acc[mf][nf][3] = expf(acc[mf][nf][3] - fm[mf][1]); s1 += acc[mf][nf][3];
        }
#pragma unroll
        for (int s = 1; s < 4; s <<= 1) {
            s0 += __shfl_xor_sync(0xffffffffu, s0, s);
            s1 += __shfl_xor_sync(0xffffffffu, s1, s);
        }
        ps[mf][0] = s0; ps[mf][1] = s1;
    }
    if (tg == 0) {
#pragma unroll
        for (int mf = 0; mf < 2; mf++) {
            sred[kw][pwb + mf * 16 + gr]     = ps[mf][0];
            sred[kw][pwb + mf * 16 + gr + 8] = ps[mf][1];
        }
    }
    __syncthreads();
#pragma unroll
    for (int mf = 0; mf < 2; mf++) {
        float inv0 = 1.f / (ps[mf][0] + sred[kw ^ 1][pwb + mf * 16 + gr]);
        float inv1 = 1.f / (ps[mf][1] + sred[kw ^ 1][pwb + mf * 16 + gr + 8]);
        size_t prow_lo = (size_t)(b * NP + p0 + pwb + mf * 16 + gr) * KK;
        size_t prow_hi = prow_lo + (size_t)8 * KK;
#pragma unroll
        for (int nf = 0; nf < 4; nf++) {
            int kc = kw * 32 + nf * 8 + tg * 2;
            u32 h, l;
            split2h(acc[mf][nf][0] * inv0, acc[mf][nf][1] * inv0, h, l);
            *(u32*)&g_zh[prow_lo + kc] = h;
            *(u32*)&g_zl[prow_lo + kc] = l;
            split2h(acc[mf][nf][2] * inv1, acc[mf][nf][3] * inv1, h, l);
            *(u32*)&g_zh[prow_hi + kc] = h;
            *(u32*)&g_zl[prow_hi + kc] = l;
        }
    }
}

// ---------------- km: xf single fp16, z hi/lo -> 2-term ----------------------
__global__ __launch_bounds__(256, 2)
void km_kernel()
{
    __shared__ __align__(16) u16 As[128 * 40];               // (c128, p32)
    __shared__ __align__(16) u16 Zh[32 * 72],  Zl[32 * 72];  // (p32, k64)

    const int ct0 = blockIdx.x * 128;
    const int b   = blockIdx.y;
    const int s   = blockIdx.z;
    const int ps0 = s * (NP / NSPLIT);
    const int tid = threadIdx.x;
    const int lane = tid & 31, wid = tid >> 5;
    const int cw = wid & 3, kw = wid >> 2;

    const u16* XF = g_xf + (size_t)b * CC * NP;
    const u16* ZH = g_zh + (size_t)b * NP * KK;
    const u16* ZL = g_zl + (size_t)b * NP * KK;

    float acc[2][4][4];
#pragma unroll
    for (int mf = 0; mf < 2; mf++)
#pragma unroll
        for (int nf = 0; nf < 4; nf++)
#pragma unroll
            for (int q = 0; q < 4; q++) acc[mf][nf][q] = 0.f;

    const u32 sa = smem_u32(As);
    const u32 szh = smem_u32(Zh), szl = smem_u32(Zl);

    const int ar0 = tid >> 2,         ag0 = (tid & 3) * 8;
    const int ar1 = (tid + 256) >> 2, ag1 = (tid & 3) * 8;
    const int zr  = tid >> 3,         zg  = (tid & 7) * 8;

    uint4 pa[2], pzh, pzl;
#define KM_PREFETCH(pc0)                                                       \
    do {                                                                       \
        pa[0] = *(const uint4*)(XF + (size_t)(ct0 + ar0) * NP + (pc0) + ag0);  \
        pa[1] = *(const uint4*)(XF + (size_t)(ct0 + ar1) * NP + (pc0) + ag1);  \
        pzh   = *(const uint4*)(ZH + (size_t)((pc0) + zr) * KK + zg);          \
        pzl   = *(const uint4*)(ZL + (size_t)((pc0) + zr) * KK + zg);          \
    } while (0)

    KM_PREFETCH(ps0);

    for (int pc0 = ps0; pc0 < ps0 + NP / NSPLIT; pc0 += 32) {
        __syncthreads();
        *(uint4*)&As[ar0 * 40 + ag0] = pa[0];
        *(uint4*)&As[ar1 * 40 + ag1] = pa[1];
        *(uint4*)&Zh[zr * 72 + zg] = pzh;
        *(uint4*)&Zl[zr * 72 + zg] = pzl;
        __syncthreads();
        if (pc0 + 32 < ps0 + NP / NSPLIT) KM_PREFETCH(pc0 + 32);

#pragma unroll
        for (int ks = 0; ks < 2; ks++) {
            u32 ah[2][4];
#pragma unroll
            for (int mf = 0; mf < 2; mf++) {
                u32 off = (((cw * 32 + mf * 16 + (lane & 15)) * 40 +
                            ks * 16 + (lane >> 4) * 8)) << 1;
                ldsm4(ah[mf], sa + off);
            }
            u32 bh[2][4], bl[2][4];
            {
                u32 row = ks * 16 + (lane & 7) + ((lane >> 3) & 1) * 8;
                u32 col = kw * 32 + ((lane >> 4) & 1) * 8;
#pragma unroll
                for (int pr = 0; pr < 2; pr++) {
                    u32 off = (row * 72 + col + pr * 16) << 1;
                    ldsm4t(bh[pr], szh + off);
                    ldsm4t(bl[pr], szl + off);
                }
            }
#pragma unroll
            for (int mf = 0; mf < 2; mf++)
#pragma unroll
                for (int nf = 0; nf < 4; nf++) {
                    const u32* bhp = &bh[nf >> 1][(nf & 1) * 2];
                    const u32* blp = &bl[nf >> 1][(nf & 1) * 2];
                    mma_fp16(acc[mf][nf], ah[mf], bhp);
                    mma_fp16(acc[mf][nf], ah[mf], blp);
                }
        }
    }
#undef KM_PREFETCH

    const int gr = lane >> 2, tg = lane & 3;
    float* out = g_mpart + ((size_t)(s * BB + b) * CC + ct0 + cw * 32) * KK;
#pragma unroll
    for (int mf = 0; mf < 2; mf++)
#pragma unroll
        for (int nf = 0; nf < 4; nf++) {
            int kc = kw * 32 + nf * 8 + tg * 2;
            int r0 = mf * 16 + gr;
            *(float2*)&out[(size_t)r0 * KK + kc] =
                make_float2(acc[mf][nf][0], acc[mf][nf][1]);
            *(float2*)&out[(size_t)(r0 + 8) * KK + kc] =
                make_float2(acc[mf][nf][2], acc[mf][nf][3]);
        }
}

// ---------------- fused norm: grid (4, BB), emits fp16 hi/lo ----------------
__global__ __launch_bounds__(1024)
void knorm_fused()
{
    const int b  = blockIdx.y;
    const int k0 = blockIdx.x * 16;
    const int tid = threadIdx.x;
    const int kl = tid & 15;
    const int cg = tid >> 4;            // 0..63, each owns 8 c-rows

    __shared__ float red[64][17];

    const size_t base = (size_t)b * CC * KK;
    const int k = k0 + kl;
    float v[8];
    float ss = 0.f;
#pragma unroll
    for (int i = 0; i < 8; i++) {
        size_t off = base + (size_t)(cg * 8 + i) * KK + k;
        float t = 0.f;
#pragma unroll
        for (int s = 0; s < NSPLIT; s++)
            t += g_mpart[(size_t)s * (BB * CC * KK) + off];
        v[i] = t;
        ss += t * t;
    }
    red[cg][kl] = ss;
    __syncthreads();
#pragma unroll
    for (int s = 32; s > 0; s >>= 1) {
        if (cg < s) red[cg][kl] += red[cg + s][kl];
        __syncthreads();
    }
    const float inv = 1.f / (EPSF + sqrtf(red[0][kl]));
    u16* mh = g_mh + base;
    u16* ml = g_ml + base;
#pragma unroll
    for (int i = 0; i < 8; i++) {
        float sv = v[i] * inv;
        __half h = __float2half_rn(sv);
        __half l = __float2half_rn(sv - __half2float(h));
        size_t off = (size_t)(cg * 8 + i) * KK + k;
        mh[off] = __half_as_ushort(h);
        ml[off] = __half_as_ushort(l);
    }
}

// ---------------- krec: rec = relu(m @ z^T), m single fp16, 2-term ----------
__global__ __launch_bounds__(256, 2)
void krec_kernel()
{
    __shared__ __align__(16) u16 Ah[128 * 40];               // (c128, k32) m hi
    __shared__ __align__(16) u16 Bh[128 * 40], Bl[128 * 40]; // (p128, k32)

    const int p0  = blockIdx.x * 128;
    const int ct0 = blockIdx.y * 128;
    const int b   = blockIdx.z;
    const int tid = threadIdx.x;
    const int lane = tid & 31, wid = tid >> 5;
    const int wm = wid & 1, wn = wid >> 1;
    const int cb = wm * 64, pb = wn * 32;

    const u16* MH = g_mh + (size_t)b * CC * KK;
    const u16* ZH = g_zh + (size_t)b * NP * KK;
    const u16* ZL = g_zl + (size_t)b * NP * KK;

    float acc[4][4][4];
#pragma unroll
    for (int mf = 0; mf < 4; mf++)
#pragma unroll
        for (int nf = 0; nf < 4; nf++)
#pragma unroll
            for (int q = 0; q < 4; q++) acc[mf][nf][q] = 0.f;

    const u32 sah = smem_u32(Ah);
    const u32 sbh = smem_u32(Bh), sbl = smem_u32(Bl);

    for (int kc0 = 0; kc0 < KK; kc0 += 32) {
#pragma unroll
        for (int it = 0; it < 2; it++) {
            int lin = tid + it * 256;
            int r = lin >> 2, g = lin & 3;
            *(uint4*)&Ah[r * 40 + g * 8] =
                *(const uint4*)(MH + (size_t)(ct0 + r) * KK + kc0 + g * 8);
        }
#pragma unroll
        for (int it = 0; it < 2; it++) {
            int lin = tid + it * 256;
            int r = lin >> 2, g = lin & 3;
            *(uint4*)&Bh[r * 40 + g * 8] =
                *(const uint4*)(ZH + (size_t)(p0 + r) * KK + kc0 + g * 8);
            *(uint4*)&Bl[r * 40 + g * 8] =
                *(const uint4*)(ZL + (size_t)(p0 + r) * KK + kc0 + g * 8);
        }
        __syncthreads();
#pragma unroll
        for (int ks = 0; ks < 2; ks++) {
            u32 ah[4][4];
            u32 a_off = (((cb + (lane & 15)) * 40 + ks * 16 + (lane >> 4) * 8)) << 1;
#pragma unroll
            for (int mf = 0; mf < 4; mf++)
                ldsm4(ah[mf], sah + a_off + mf * (16 * 40 * 2));
            u32 bh[2][4], bl[2][4];
            u32 brow = pb + ((lane >> 4) & 1) * 8 + (lane & 7);
            u32 bcol = ks * 16 + ((lane >> 3) & 1) * 8;
#pragma unroll
            for (int pr = 0; pr < 2; pr++) {
                u32 boff = ((brow + pr * 16) * 40 + bcol) << 1;
                ldsm4(bh[pr], sbh + boff);
                ldsm4(bl[pr], sbl + boff);
            }
#pragma unroll
            for (int mf = 0; mf < 4; mf++)
#pragma unroll
                for (int nf = 0; nf < 4; nf++) {
                    const u32* bhp = &bh[nf >> 1][(nf & 1) * 2];
                    const u32* blp = &bl[nf >> 1][(nf & 1) * 2];
                    mma_fp16(acc[mf][nf], ah[mf], bhp);
                    mma_fp16(acc[mf][nf], ah[mf], blp);
                }
        }
        __syncthreads();
    }

    const int g = lane >> 2, tg = lane & 3;
    u16* rh = g_rech + (size_t)b * CC * NP;
#pragma unroll
    for (int mf = 0; mf < 4; mf++) {
        int c_lo = ct0 + cb + mf * 16 + g;
        int c_hi = c_lo + 8;
#pragma unroll
        for (int nf = 0; nf < 4; nf++) {
            int pc = p0 + pb + nf * 8 + tg * 2;
            *(u32*)&rh[(size_t)c_lo * NP + pc] =
                pack2h(fmaxf(acc[mf][nf][0], 0.f), fmaxf(acc[mf][nf][1], 0.f));
            *(u32*)&rh[(size_t)c_hi * NP + pc] =
                pack2h(fmaxf(acc[mf][nf][2], 0.f), fmaxf(acc[mf][nf][3], 0.f));
        }
    }
}

// ---------------- launch ----------------------------------------------------
extern "C" void kernel_launch(void* const* d_in, const int* in_sizes, int n_in,
                              void* d_out, int out_size)
{
    (void)in_sizes; (void)n_in; (void)out_size;
    const float* x     = (const float*)d_in[0];
    const float* w1    = (const float*)d_in[1];
    const float* b1    = (const float*)d_in[2];
    const float* mu    = (const float*)d_in[3];
    const float* w2    = (const float*)d_in[4];
    const float* gamma = (const float*)d_in[5];
    const float* beta  = (const float*)d_in[6];
    const float* mean  = (const float*)d_in[7];
    const float* var   = (const float*)d_in[8];
    float* out = (float*)d_out;

    cudaFuncSetAttribute(hconv<0>, cudaFuncAttributeMaxDynamicSharedMemorySize,
                         HCONV_SMEM);
    cudaFuncSetAttribute(hconv<1>, cudaFuncAttributeMaxDynamicSharedMemorySize,
                         HCONV_SMEM);

    kcvt_all<<<XBLOCKS + WBLOCKS + MUBLOCKS, 256>>>(x, w1, w2, mu);

    hconv<0><<<dim3(NP / 128, CC / 128, BB), 128, HCONV_SMEM>>>(
        nullptr, b1, nullptr, nullptr, nullptr);

    for (int st = 0; st < 3; st++) {
        kz_kernel<<<dim3(NP / 128, BB), 256>>>(st > 0 ? 1 : 0);
        km_kernel<<<dim3(CC / 128, BB, NSPLIT), 256>>>();
        knorm_fused<<<dim3(4, BB), 1024>>>();
    }

    krec_kernel<<<dim3(NP / 128, CC / 128, BB), 256>>>();

    hconv<1><<<dim3(NP / 128, CC / 128, BB), 128, HCONV_SMEM>>>(
        out, gamma, beta, mean, var);
}

// round 17
// speedup vs baseline: 1.3681x; 1.1545x over previous
#include <cuda_runtime.h>
#include <cuda_bf16.h>
#include <cuda_fp16.h>

#define CC 512
#define NP 4096
#define KK 64
#define BB 16
#define NSPLIT 4
#define EPSF 1e-6f

typedef unsigned long long u64;
typedef unsigned int u32;
typedef unsigned short u16;

// ---------------- scratch (static device globals) ---------------------------
__device__ u16 g_xh[(size_t)BB * CC * NP];   // x fp16 single (b,c,p)
__device__ u16 g_wf1[(size_t)CC * CC];       // w1 fp16 single
__device__ u16 g_wf2[(size_t)CC * CC];       // w2 fp16 single
__device__ u16 g_muh[(size_t)CC * KK], g_mul[(size_t)CC * KK];   // fp16 hi/lo
__device__ u16 g_xf[(size_t)BB * CC * NP];   // conv1 out fp16 single (b,c,p)
__device__ u16 g_zh[(size_t)BB * NP * KK];   // z hi fp16 (b,p,k)
__device__ u16 g_zl[(size_t)BB * NP * KK];
__device__ u16 g_mh[(size_t)BB * CC * KK];   // m hi fp16 (b,c,k)
__device__ u16 g_ml[(size_t)BB * CC * KK];
__device__ u16 g_rech[(size_t)BB * CC * NP]; // relu(rec) fp16 single (b,c,p)
__device__ float g_mpart[(size_t)NSPLIT * BB * CC * KK];

// ---------------- helpers ----------------------------------------------------
__device__ __forceinline__ u32 smem_u32(const void* p) {
    u32 a;
    asm("{ .reg .u64 t; cvta.to.shared.u64 t, %1; cvt.u32.u64 %0, t; }"
        : "=r"(a) : "l"(p));
    return a;
}
__device__ __forceinline__ void ldsm4(u32* r, u32 addr) {
    asm volatile("ldmatrix.sync.aligned.m8n8.x4.shared.b16 {%0,%1,%2,%3}, [%4];"
                 : "=r"(r[0]), "=r"(r[1]), "=r"(r[2]), "=r"(r[3]) : "r"(addr));
}
__device__ __forceinline__ void ldsm4t(u32* r, u32 addr) {
    asm volatile("ldmatrix.sync.aligned.m8n8.x4.trans.shared.b16 {%0,%1,%2,%3}, [%4];"
                 : "=r"(r[0]), "=r"(r[1]), "=r"(r[2]), "=r"(r[3]) : "r"(addr));
}
__device__ __forceinline__ void mma_fp16(float* d, const u32* a, const u32* b) {
    asm volatile(
        "mma.sync.aligned.m16n8k16.row.col.f32.f16.f16.f32 "
        "{%0,%1,%2,%3}, {%4,%5,%6,%7}, {%8,%9}, {%0,%1,%2,%3};"
        : "+f"(d[0]), "+f"(d[1]), "+f"(d[2]), "+f"(d[3])
        : "r"(a[0]), "r"(a[1]), "r"(a[2]), "r"(a[3]), "r"(b[0]), "r"(b[1]));
}
__device__ __forceinline__ void split2h(float v0, float v1, u32& hi, u32& lo) {
    __half h0 = __float2half_rn(v0);
    __half h1 = __float2half_rn(v1);
    __half l0 = __float2half_rn(v0 - __half2float(h0));
    __half l1 = __float2half_rn(v1 - __half2float(h1));
    hi = (u32)__half_as_ushort(h0) | ((u32)__half_as_ushort(h1) << 16);
    lo = (u32)__half_as_ushort(l0) | ((u32)__half_as_ushort(l1) << 16);
}
__device__ __forceinline__ u32 pack2h(float v0, float v1) {
    __half h0 = __float2half_rn(v0);
    __half h1 = __float2half_rn(v1);
    return (u32)__half_as_ushort(h0) | ((u32)__half_as_ushort(h1) << 16);
}
__device__ __forceinline__ void cpa16(u32 dst, const void* src) {
    asm volatile("cp.async.cg.shared.global [%0], [%1], 16;"
                 :: "r"(dst), "l"(src));
}
#define CPA_COMMIT() asm volatile("cp.async.commit_group;")
#define CPA_WAIT(n)  asm volatile("cp.async.wait_group %0;" :: "n"(n))

// ---------------- fused convert kernel (x + w1/w2 + mu in one launch) -------
#define XBLOCKS 32768          // BB*CC*NP / 1024
#define WBLOCKS 512            // CC*CC / 512
#define MUBLOCKS 64            // CC*KK / 512
__global__ void kcvt_all(const float* __restrict__ x,
                         const float* __restrict__ w1,
                         const float* __restrict__ w2,
                         const float* __restrict__ mu)
{
    int bx = blockIdx.x;
    if (bx < XBLOCKS) {
        size_t i4 = ((size_t)bx * 256 + threadIdx.x) * 4;
        float4 v = *(const float4*)&x[i4];
        *(uint2*)&g_xh[i4] = make_uint2(pack2h(v.x, v.y), pack2h(v.z, v.w));
    } else if (bx < XBLOCKS + WBLOCKS) {
        size_t i2 = ((size_t)(bx - XBLOCKS) * 256 + threadIdx.x) * 2;
        *(u32*)&g_wf1[i2] = pack2h(w1[i2], w1[i2 + 1]);
        *(u32*)&g_wf2[i2] = pack2h(w2[i2], w2[i2 + 1]);
    } else {
        size_t i2 = ((size_t)(bx - XBLOCKS - WBLOCKS) * 256 + threadIdx.x) * 2;
        u32 h, l;
        split2h(mu[i2], mu[i2 + 1], h, l);
        *(u32*)&g_muh[i2] = h; *(u32*)&g_mul[i2] = l;
    }
}

// ---------------- conv GEMM: 1-term fp16, 128 thr, 64x64 tiles, 4-stage -----
// EPI=0: B = x fp16, bias -> g_xf fp16 ; EPI=1: B = rec fp16, BN -> OUT fp32
#define APITCH 40
#define BPITCH 136
#define AH_OFF 0
#define BH_OFF 10240
#define STAGE_B 18944
#define NSTAGE 4
#define NCH 16
#define HCONV_SMEM (STAGE_B * NSTAGE)

template <int EPI>
__global__ __launch_bounds__(128, 2)
void hconv(float* __restrict__ OUT,
           const float* __restrict__ e0, const float* __restrict__ e1,
           const float* __restrict__ e2, const float* __restrict__ e3)
{
    extern __shared__ __align__(16) char dsm[];
    const u32 sb = smem_u32(dsm);

    const int p0 = blockIdx.x * 128;
    const int o0 = blockIdx.y * 128;
    const int b  = blockIdx.z;
    const int tid = threadIdx.x;
    const int lane = tid & 31, wid = tid >> 5;
    const int ob = (wid & 1) * 64, pb = (wid >> 1) * 64;

    const u16* WH = (EPI == 0) ? g_wf1 : g_wf2;
    const u16* IH = ((EPI == 0) ? g_xh : g_rech) + (size_t)b * CC * NP;

    float acc[4][8][4];
#pragma unroll
    for (int mf = 0; mf < 4; mf++)
#pragma unroll
        for (int nf = 0; nf < 8; nf++)
#pragma unroll
            for (int q = 0; q < 4; q++) acc[mf][nf][q] = 0.f;

    const int arow = tid >> 2, au = (tid & 3) * 8;
    const int brow = tid >> 4, bu = (tid & 15) * 8;

#define LOAD_CHUNK(st, c0)                                                      \
    do {                                                                        \
        u32 base = sb + (st) * STAGE_B;                                         \
        _Pragma("unroll")                                                       \
        for (int i = 0; i < 4; i++) {                                           \
            int r = arow + i * 32;                                              \
            cpa16(base + AH_OFF + (r * APITCH + au) * 2,                        \
                  WH + (size_t)(o0 + r) * CC + (c0) + au);                      \
        }                                                                       \
        _Pragma("unroll")                                                       \
        for (int i = 0; i < 4; i++) {                                           \
            int r = brow + i * 8;                                               \
            cpa16(base + BH_OFF + (r * BPITCH + bu) * 2,                        \
                  IH + (size_t)((c0) + r) * NP + p0 + bu);                      \
        }                                                                       \
        CPA_COMMIT();                                                           \
    } while (0)

    LOAD_CHUNK(0, 0);
    LOAD_CHUNK(1, 32);
    LOAD_CHUNK(2, 64);

    const u32 a_lane = ((ob + (lane & 15)) * APITCH + (lane >> 4) * 8) * 2;
    const u32 b_rbase = (lane & 7) + ((lane >> 3) & 1) * 8;
    const u32 b_col   = pb + ((lane >> 4) & 1) * 8;

    for (int ch = 0; ch < NCH; ch++) {
        if (ch < NCH - 2)      { CPA_WAIT(2); }
        else if (ch == NCH - 2){ CPA_WAIT(1); }
        else                   { CPA_WAIT(0); }
        __syncthreads();
        if (ch < NCH - 3) LOAD_CHUNK((ch + 3) % NSTAGE, (ch + 3) * 32);

        const u32 stb = sb + (ch % NSTAGE) * STAGE_B;
#pragma unroll
        for (int ks = 0; ks < 2; ks++) {
            u32 ah[4][4];
            const u32 abase = stb + a_lane + ks * 32;
#pragma unroll
            for (int mf = 0; mf < 4; mf++)
                ldsm4(ah[mf], abase + AH_OFF + mf * (16 * APITCH * 2));
            const u32 brw = ks * 16 + b_rbase;
            const u32 bbase = stb + (brw * BPITCH + b_col) * 2;
#pragma unroll
            for (int pr = 0; pr < 4; pr++) {
                u32 bh[4];
                ldsm4t(bh, bbase + BH_OFF + pr * 32);
#pragma unroll
                for (int mf = 0; mf < 4; mf++) {
                    mma_fp16(acc[mf][pr * 2 + 0], ah[mf], &bh[0]);
                    mma_fp16(acc[mf][pr * 2 + 1], ah[mf], &bh[2]);
                }
            }
        }
    }

    const int g = lane >> 2, tg = lane & 3;
#pragma unroll
    for (int mf = 0; mf < 4; mf++) {
        int o_lo = o0 + ob + mf * 16 + g;
        int o_hi = o_lo + 8;
        if (EPI == 0) {
            float add_lo = e0[o_lo], add_hi = e0[o_hi];
            u16* xf = g_xf + (size_t)b * CC * NP;
#pragma unroll
            for (int nf = 0; nf < 8; nf++) {
                int pc = p0 + pb + nf * 8 + tg * 2;
                *(u32*)&xf[(size_t)o_lo * NP + pc] =
                    pack2h(acc[mf][nf][0] + add_lo, acc[mf][nf][1] + add_lo);
                *(u32*)&xf[(size_t)o_hi * NP + pc] =
                    pack2h(acc[mf][nf][2] + add_hi, acc[mf][nf][3] + add_hi);
            }
        } else {
            float mul_lo = e0[o_lo] * rsqrtf(e3[o_lo] + 1e-5f);
            float add_lo = e1[o_lo] - e2[o_lo] * mul_lo;
            float mul_hi = e0[o_hi] * rsqrtf(e3[o_hi] + 1e-5f);
            float add_hi = e1[o_hi] - e2[o_hi] * mul_hi;
            float* outb = OUT + (size_t)b * CC * NP;
#pragma unroll
            for (int nf = 0; nf < 8; nf++) {
                int pc = p0 + pb + nf * 8 + tg * 2;
                float2 v0, v1;
                v0.x = acc[mf][nf][0] * mul_lo + add_lo;
                v0.y = acc[mf][nf][1] * mul_lo + add_lo;
                v1.x = acc[mf][nf][2] * mul_hi + add_hi;
                v1.y = acc[mf][nf][3] * mul_hi + add_hi;
                *(float2*)&outb[(size_t)o_lo * NP + pc] = v0;
                *(float2*)&outb[(size_t)o_hi * NP + pc] = v1;
            }
        }
    }
#undef LOAD_CHUNK
}

// ---------------- kz: xf single fp16, m hi/lo -> 2-term ----------------------
__global__ __launch_bounds__(256, 2)
void kz_kernel(int use_gm)
{
    __shared__ __align__(16) u16 Xs[32 * 136];               // (c32, p128)
    __shared__ __align__(16) u16 Mh[32 * 72],  Ml[32 * 72];  // (c32, k64)
    __shared__ float sred[2][128];

    const int p0 = blockIdx.x * 128;
    const int b  = blockIdx.y;
    const int tid = threadIdx.x;
    const int lane = tid & 31, wid = tid >> 5;
    const int pg = wid & 3, kw = wid >> 2;
    const int pwb = pg * 32;

    const u16* XF = g_xf + (size_t)b * CC * NP;
    const u16* MH = use_gm ? (g_mh + (size_t)b * CC * KK) : g_muh;
    const u16* ML = use_gm ? (g_ml + (size_t)b * CC * KK) : g_mul;

    float acc[2][4][4];
#pragma unroll
    for (int mf = 0; mf < 2; mf++)
#pragma unroll
        for (int nf = 0; nf < 4; nf++)
#pragma unroll
            for (int q = 0; q < 4; q++) acc[mf][nf][q] = 0.f;

    const u32 sx = smem_u32(Xs);
    const u32 smh = smem_u32(Mh), sml = smem_u32(Ml);

    const int xr0 = tid >> 4,           xg0 = (tid & 15) * 8;
    const int xr1 = (tid + 256) >> 4,   xg1 = (tid & 15) * 8;
    const int mr  = tid >> 3,           mg  = (tid & 7) * 8;

    uint4 px[2], pmh, pml;
#define KZ_PREFETCH(c0)                                                        \
    do {                                                                       \
        px[0] = *(const uint4*)(XF + (size_t)((c0) + xr0) * NP + p0 + xg0);    \
        px[1] = *(const uint4*)(XF + (size_t)((c0) + xr1) * NP + p0 + xg1);    \
        pmh   = *(const uint4*)(MH + (size_t)((c0) + mr) * KK + mg);           \
        pml   = *(const uint4*)(ML + (size_t)((c0) + mr) * KK + mg);           \
    } while (0)

    KZ_PREFETCH(0);

    for (int c0 = 0; c0 < CC; c0 += 32) {
        __syncthreads();
        *(uint4*)&Xs[xr0 * 136 + xg0] = px[0];
        *(uint4*)&Xs[xr1 * 136 + xg1] = px[1];
        *(uint4*)&Mh[mr * 72 + mg] = pmh;
        *(uint4*)&Ml[mr * 72 + mg] = pml;
        __syncthreads();
        if (c0 + 32 < CC) KZ_PREFETCH(c0 + 32);

#pragma unroll
        for (int ks = 0; ks < 2; ks++) {
            u32 ah[2][4];
#pragma unroll
            for (int mf = 0; mf < 2; mf++) {
                u32 row = ks * 16 + (lane & 7) + ((lane >> 4) & 1) * 8;
                u32 col = pwb + mf * 16 + ((lane >> 3) & 1) * 8;
                u32 off = (row * 136 + col) << 1;
                ldsm4t(ah[mf], sx + off);
            }
            u32 bh[2][4], bl[2][4];
            {
                u32 row = ks * 16 + (lane & 7) + ((lane >> 3) & 1) * 8;
                u32 col = kw * 32 + ((lane >> 4) & 1) * 8;
#pragma unroll
                for (int pr = 0; pr < 2; pr++) {
                    u32 off = (row * 72 + col + pr * 16) << 1;
                    ldsm4t(bh[pr], smh + off);
                    ldsm4t(bl[pr], sml + off);
                }
            }
#pragma unroll
            for (int mf = 0; mf < 2; mf++)
#pragma unroll
                for (int nf = 0; nf < 4; nf++) {
                    const u32* bhp = &bh[nf >> 1][(nf & 1) * 2];
                    const u32* blp = &bl[nf >> 1][(nf & 1) * 2];
                    mma_fp16(acc[mf][nf], ah[mf], bhp);
                    mma_fp16(acc[mf][nf], ah[mf], blp);
                }
        }
    }
#undef KZ_PREFETCH

    // ---- softmax over k=64 split across 2 k-warps ----
    const int gr = lane >> 2, tg = lane & 3;
    float pm[2][2];
#pragma unroll
    for (int mf = 0; mf < 2; mf++) {
        float m0 = -1e30f, m1 = -1e30f;
#pragma unroll
        for (int nf = 0; nf < 4; nf++) {
            m0 = fmaxf(m0, fmaxf(acc[mf][nf][0], acc[mf][nf][1]));
            m1 = fmaxf(m1, fmaxf(acc[mf][nf][2], acc[mf][nf][3]));
        }
#pragma unroll
        for (int s = 1; s < 4; s <<= 1) {
            m0 = fmaxf(m0, __shfl_xor_sync(0xffffffffu, m0, s));
            m1 = fmaxf(m1, __shfl_xor_sync(0xffffffffu, m1, s));
        }
        pm[mf][0] = m0; pm[mf][1] = m1;
    }
    if (tg == 0) {
#pragma unroll
        for (int mf = 0; mf < 2; mf++) {
            sred[kw][pwb + mf * 16 + gr]     = pm[mf][0];
            sred[kw][pwb + mf * 16 + gr + 8] = pm[mf][1];
        }
    }
    __syncthreads();
    float fm[2][2];
#pragma unroll
    for (int mf = 0; mf < 2; mf++) {
        fm[mf][0] = fmaxf(pm[mf][0], sred[kw ^ 1][pwb + mf * 16 + gr]);
        fm[mf][1] = fmaxf(pm[mf][1], sred[kw ^ 1][pwb + mf * 16 + gr + 8]);
    }
    __syncthreads();
    float ps[2][2];
#pragma unroll
    for (int mf = 0; mf < 2; mf++) {
        float s0 = 0.f, s1 = 0.f;
#pragma unroll
        for (int nf = 0; nf < 4; nf++) {
            acc[mf][nf][0] = expf(acc[mf][nf][0] - fm[mf][0]); s0 += acc[mf][nf][0];
            acc[mf][nf][1] = expf(acc[mf][nf][1] - fm[mf][0]); s0 += acc[mf][nf][1];
            acc[mf][nf][2] = expf(acc[mf][nf][2] - fm[mf][1]); s1 += acc[mf][nf][2];
            acc[mf][nf][3] = expf(acc[mf][nf][3] - fm[mf][1]); s1 += acc[mf][nf][3];
        }
#pragma unroll
        for (int s = 1; s < 4; s <<= 1) {
            s0 += __shfl_xor_sync(0xffffffffu, s0, s);
            s1 += __shfl_xor_sync(0xffffffffu, s1, s);
        }
        ps[mf][0] = s0; ps[mf][1] = s1;
    }
    if (tg == 0) {
#pragma unroll
        for (int mf = 0; mf < 2; mf++) {
            sred[kw][pwb + mf * 16 + gr]     = ps[mf][0];
            sred[kw][pwb + mf * 16 + gr + 8] = ps[mf][1];
        }
    }
    __syncthreads();
#pragma unroll
    for (int mf = 0; mf < 2; mf++) {
        float inv0 = 1.f / (ps[mf][0] + sred[kw ^ 1][pwb + mf * 16 + gr]);
        float inv1 = 1.f / (ps[mf][1] + sred[kw ^ 1][pwb + mf * 16 + gr + 8]);
        size_t prow_lo = (size_t)(b * NP + p0 + pwb + mf * 16 + gr) * KK;
        size_t prow_hi = prow_lo + (size_t)8 * KK;
#pragma unroll
        for (int nf = 0; nf < 4; nf++) {
            int kc = kw * 32 + nf * 8 + tg * 2;
            u32 h, l;
            split2h(acc[mf][nf][0] * inv0, acc[mf][nf][1] * inv0, h, l);
            *(u32*)&g_zh[prow_lo + kc] = h;
            *(u32*)&g_zl[prow_lo + kc] = l;
            split2h(acc[mf][nf][2] * inv1, acc[mf][nf][3] * inv1, h, l);
            *(u32*)&g_zh[prow_hi + kc] = h;
            *(u32*)&g_zl[prow_hi + kc] = l;
        }
    }
}

// ---------------- km: xf single fp16, z hi/lo -> 2-term ----------------------
__global__ __launch_bounds__(256, 2)
void km_kernel()
{
    __shared__ __align__(16) u16 As[128 * 40];               // (c128, p32)
    __shared__ __align__(16) u16 Zh[32 * 72],  Zl[32 * 72];  // (p32, k64)

    const int ct0 = blockIdx.x * 128;
    const int b   = blockIdx.y;
    const int s   = blockIdx.z;
    const int ps0 = s * (NP / NSPLIT);
    const int tid = threadIdx.x;
    const int lane = tid & 31, wid = tid >> 5;
    const int cw = wid & 3, kw = wid >> 2;

    const u16* XF = g_xf + (size_t)b * CC * NP;
    const u16* ZH = g_zh + (size_t)b * NP * KK;
    const u16* ZL = g_zl + (size_t)b * NP * KK;

    float acc[2][4][4];
#pragma unroll
    for (int mf = 0; mf < 2; mf++)
#pragma unroll
        for (int nf = 0; nf < 4; nf++)
#pragma unroll
            for (int q = 0; q < 4; q++) acc[mf][nf][q] = 0.f;

    const u32 sa = smem_u32(As);
    const u32 szh = smem_u32(Zh), szl = smem_u32(Zl);

    const int ar0 = tid >> 2,         ag0 = (tid & 3) * 8;
    const int ar1 = (tid + 256) >> 2, ag1 = (tid & 3) * 8;
    const int zr  = tid >> 3,         zg  = (tid & 7) * 8;

    uint4 pa[2], pzh, pzl;
#define KM_PREFETCH(pc0)                                                       \
    do {                                                                       \
        pa[0] = *(const uint4*)(XF + (size_t)(ct0 + ar0) * NP + (pc0) + ag0);  \
        pa[1] = *(const uint4*)(XF + (size_t)(ct0 + ar1) * NP + (pc0) + ag1);  \
        pzh   = *(const uint4*)(ZH + (size_t)((pc0) + zr) * KK + zg);          \
        pzl   = *(const uint4*)(ZL + (size_t)((pc0) + zr) * KK + zg);          \
    } while (0)

    KM_PREFETCH(ps0);

    for (int pc0 = ps0; pc0 < ps0 + NP / NSPLIT; pc0 += 32) {
        __syncthreads();
        *(uint4*)&As[ar0 * 40 + ag0] = pa[0];
        *(uint4*)&As[ar1 * 40 + ag1] = pa[1];
        *(uint4*)&Zh[zr * 72 + zg] = pzh;
        *(uint4*)&Zl[zr * 72 + zg] = pzl;
        __syncthreads();
        if (pc0 + 32 < ps0 + NP / NSPLIT) KM_PREFETCH(pc0 + 32);

#pragma unroll
        for (int ks = 0; ks < 2; ks++) {
            u32 ah[2][4];
#pragma unroll
            for (int mf = 0; mf < 2; mf++) {
                u32 off = (((cw * 32 + mf * 16 + (lane & 15)) * 40 +
                            ks * 16 + (lane >> 4) * 8)) << 1;
                ldsm4(ah[mf], sa + off);
            }
            u32 bh[2][4], bl[2][4];
            {
                u32 row = ks * 16 + (lane & 7) + ((lane >> 3) & 1) * 8;
                u32 col = kw * 32 + ((lane >> 4) & 1) * 8;
#pragma unroll
                for (int pr = 0; pr < 2; pr++) {
                    u32 off = (row * 72 + col + pr * 16) << 1;
                    ldsm4t(bh[pr], szh + off);
                    ldsm4t(bl[pr], szl + off);
                }
            }
#pragma unroll
            for (int mf = 0; mf < 2; mf++)
#pragma unroll
                for (int nf = 0; nf < 4; nf++) {
                    const u32* bhp = &bh[nf >> 1][(nf & 1) * 2];
                    const u32* blp = &bl[nf >> 1][(nf & 1) * 2];
                    mma_fp16(acc[mf][nf], ah[mf], bhp);
                    mma_fp16(acc[mf][nf], ah[mf], blp);
                }
        }
    }
#undef KM_PREFETCH

    const int gr = lane >> 2, tg = lane & 3;
    float* out = g_mpart + ((size_t)(s * BB + b) * CC + ct0 + cw * 32) * KK;
#pragma unroll
    for (int mf = 0; mf < 2; mf++)
#pragma unroll
        for (int nf = 0; nf < 4; nf++) {
            int kc = kw * 32 + nf * 8 + tg * 2;
            int r0 = mf * 16 + gr;
            *(float2*)&out[(size_t)r0 * KK + kc] =
                make_float2(acc[mf][nf][0], acc[mf][nf][1]);
            *(float2*)&out[(size_t)(r0 + 8) * KK + kc] =
                make_float2(acc[mf][nf][2], acc[mf][nf][3]);
        }
}

// ---------------- fused norm: grid (4, BB), emits fp16 hi/lo ----------------
__global__ __launch_bounds__(1024)
void knorm_fused()
{
    const int b  = blockIdx.y;
    const int k0 = blockIdx.x * 16;
    const int tid = threadIdx.x;
    const int kl = tid & 15;
    const int cg = tid >> 4;            // 0..63, each owns 8 c-rows

    __shared__ float red[64][17];

    const size_t base = (size_t)b * CC * KK;
    const int k = k0 + kl;
    float v[8];
    float ss = 0.f;
#pragma unroll
    for (int i = 0; i < 8; i++) {
        size_t off = base + (size_t)(cg * 8 + i) * KK + k;
        float t = 0.f;
#pragma unroll
        for (int s = 0; s < NSPLIT; s++)
            t += g_mpart[(size_t)s * (BB * CC * KK) + off];
        v[i] = t;
        ss += t * t;
    }
    red[cg][kl] = ss;
    __syncthreads();
#pragma unroll
    for (int s = 32; s > 0; s >>= 1) {
        if (cg < s) red[cg][kl] += red[cg + s][kl];
        __syncthreads();
    }
    const float inv = 1.f / (EPSF + sqrtf(red[0][kl]));
    u16* mh = g_mh + base;
    u16* ml = g_ml + base;
#pragma unroll
    for (int i = 0; i < 8; i++) {
        float sv = v[i] * inv;
        __half h = __float2half_rn(sv);
        __half l = __float2half_rn(sv - __half2float(h));
        size_t off = (size_t)(cg * 8 + i) * KK + k;
        mh[off] = __half_as_ushort(h);
        ml[off] = __half_as_ushort(l);
    }
}

// ---------------- krec: rec = relu(m @ z^T), m single fp16, 2-term ----------
__global__ __launch_bounds__(256, 2)
void krec_kernel()
{
    __shared__ __align__(16) u16 Ah[128 * 40];               // (c128, k32) m hi
    __shared__ __align__(16) u16 Bh[128 * 40], Bl[128 * 40]; // (p128, k32)

    const int p0  = blockIdx.x * 128;
    const int ct0 = blockIdx.y * 128;
    const int b   = blockIdx.z;
    const int tid = threadIdx.x;
    const int lane = tid & 31, wid = tid >> 5;
    const int wm = wid & 1, wn = wid >> 1;
    const int cb = wm * 64, pb = wn * 32;

    const u16* MH = g_mh + (size_t)b * CC * KK;
    const u16* ZH = g_zh + (size_t)b * NP * KK;
    const u16* ZL = g_zl + (size_t)b * NP * KK;

    float acc[4][4][4];
#pragma unroll
    for (int mf = 0; mf < 4; mf++)
#pragma unroll
        for (int nf = 0; nf < 4; nf++)
#pragma unroll
            for (int q = 0; q < 4; q++) acc[mf][nf][q] = 0.f;

    const u32 sah = smem_u32(Ah);
    const u32 sbh = smem_u32(Bh), sbl = smem_u32(Bl);

    for (int kc0 = 0; kc0 < KK; kc0 += 32) {
#pragma unroll
        for (int it = 0; it < 2; it++) {
            int lin = tid + it * 256;
            int r = lin >> 2, g = lin & 3;
            *(uint4*)&Ah[r * 40 + g * 8] =
                *(const uint4*)(MH + (size_t)(ct0 + r) * KK + kc0 + g * 8);
        }
#pragma unroll
        for (int it = 0; it < 2; it++) {
            int lin = tid + it * 256;
            int r = lin >> 2, g = lin & 3;
            *(uint4*)&Bh[r * 40 + g * 8] =
                *(const uint4*)(ZH + (size_t)(p0 + r) * KK + kc0 + g * 8);
            *(uint4*)&Bl[r * 40 + g * 8] =
                *(const uint4*)(ZL + (size_t)(p0 + r) * KK + kc0 + g * 8);
        }
        __syncthreads();
#pragma unroll
        for (int ks = 0; ks < 2; ks++) {
            u32 ah[4][4];
            u32 a_off = (((cb + (lane & 15)) * 40 + ks * 16 + (lane >> 4) * 8)) << 1;
#pragma unroll
            for (int mf = 0; mf < 4; mf++)
                ldsm4(ah[mf], sah + a_off + mf * (16 * 40 * 2));
            u32 bh[2][4], bl[2][4];
            u32 brow = pb + ((lane >> 4) & 1) * 8 + (lane & 7);
            u32 bcol = ks * 16 + ((lane >> 3) & 1) * 8;
#pragma unroll
            for (int pr = 0; pr < 2; pr++) {
                u32 boff = ((brow + pr * 16) * 40 + bcol) << 1;
                ldsm4(bh[pr], sbh + boff);
                ldsm4(bl[pr], sbl + boff);
            }
#pragma unroll
            for (int mf = 0; mf < 4; mf++)
#pragma unroll
                for (int nf = 0; nf < 4; nf++) {
                    const u32* bhp = &bh[nf >> 1][(nf & 1) * 2];
                    const u32* blp = &bl[nf >> 1][(nf & 1) * 2];
                    mma_fp16(acc[mf][nf], ah[mf], bhp);
                    mma_fp16(acc[mf][nf], ah[mf], blp);
                }
        }
        __syncthreads();
    }

    const int g = lane >> 2, tg = lane & 3;
    u16* rh = g_rech + (size_t)b * CC * NP;
#pragma unroll
    for (int mf = 0; mf < 4; mf++) {
        int c_lo = ct0 + cb + mf * 16 + g;
        int c_hi = c_lo + 8;
#pragma unroll
        for (int nf = 0; nf < 4; nf++) {
            int pc = p0 + pb + nf * 8 + tg * 2;
            *(u32*)&rh[(size_t)c_lo * NP + pc] =
                pack2h(fmaxf(acc[mf][nf][0], 0.f), fmaxf(acc[mf][nf][1], 0.f));
            *(u32*)&rh[(size_t)c_hi * NP + pc] =
                pack2h(fmaxf(acc[mf][nf][2], 0.f), fmaxf(acc[mf][nf][3], 0.f));
        }
    }
}

// ---------------- launch ----------------------------------------------------
extern "C" void kernel_launch(void* const* d_in, const int* in_sizes, int n_in,
                              void* d_out, int out_size)
{
    (void)in_sizes; (void)n_in; (void)out_size;
    const float* x     = (const float*)d_in[0];
    const float* w1    = (const float*)d_in[1];
    const float* b1    = (const float*)d_in[2];
    const float* mu    = (const float*)d_in[3];
    const float* w2    = (const float*)d_in[4];
    const float* gamma = (const float*)d_in[5];
    const float* beta  = (const float*)d_in[6];
    const float* mean  = (const float*)d_in[7];
    const float* var   = (const float*)d_in[8];
    float* out = (float*)d_out;

    cudaFuncSetAttribute(hconv<0>, cudaFuncAttributeMaxDynamicSharedMemorySize,
                         HCONV_SMEM);
    cudaFuncSetAttribute(hconv<1>, cudaFuncAttributeMaxDynamicSharedMemorySize,
                         HCONV_SMEM);

    kcvt_all<<<XBLOCKS + WBLOCKS + MUBLOCKS, 256>>>(x, w1, w2, mu);

    hconv<0><<<dim3(NP / 128, CC / 128, BB), 128, HCONV_SMEM>>>(
        nullptr, b1, nullptr, nullptr, nullptr);

    for (int st = 0; st < 3; st++) {
        kz_kernel<<<dim3(NP / 128, BB), 256>>>(st > 0 ? 1 : 0);
        km_kernel<<<dim3(CC / 128, BB, NSPLIT), 256>>>();
        knorm_fused<<<dim3(4, BB), 1024>>>();
    }

    krec_kernel<<<dim3(NP / 128, CC / 128, BB), 256>>>();

    hconv<1><<<dim3(NP / 128, CC / 128, BB), 128, HCONV_SMEM>>>(
        out, gamma, beta, mean, var);
}